// round 9
// baseline (speedup 1.0000x reference)
#include <cuda_runtime.h>
#include <cuda_bf16.h>
#include <cstdint>

// HartleySpectralConv2d B=16,CI=CO=64,H=W=256, modes 64x64.
// Split-bf16 GEMMs on mma.sync.m16n8k16; 4-stage cp.async ring, k=16 chunks.

using bf16 = __nv_bfloat16;
using u32 = uint32_t; using ull = unsigned long long;

__device__ bf16 g_Tch[128 * 256], g_Tcl[128 * 256];       // [j][n] K-major
__device__ bf16 g_A5h[2 * 256 * 64], g_A5l[2 * 256 * 64]; // [(c*256+m)][s1]
__device__ bf16 g_T5h[256 * 128], g_T5l[256 * 128];       // [n][c*64+s2]
__device__ bf16 g_Uth[1024 * 128 * 256], g_Utl[1024 * 128 * 256]; // [img][j][m]
__device__ float g_Wt[4096 * 4096];                       // [mode][i*64+o]
__device__ float g_CS[2 * 4096 * 1024];                   // [comp][mode][ci*16+b]
__device__ bf16 g_Tth[1024 * 4096], g_Ttl[1024 * 4096];   // [img][s2*64+s1]
__device__ bf16 g_Wh[1024 * 256 * 128], g_Wl[1024 * 256 * 128]; // [img][m][k]

// ---------------- helpers ----------------
__device__ __forceinline__ u32 smem_u32(const void* p) {
    u32 a;
    asm("{ .reg .u64 t; cvta.to.shared.u64 t, %1; cvt.u32.u64 %0, t; }" : "=r"(a) : "l"(p));
    return a;
}
__device__ __forceinline__ void ldsm4(u32* r, u32 a) {
    asm volatile("ldmatrix.sync.aligned.m8n8.x4.shared.b16 {%0,%1,%2,%3}, [%4];"
                 : "=r"(r[0]), "=r"(r[1]), "=r"(r[2]), "=r"(r[3]) : "r"(a));
}
__device__ __forceinline__ void mmabf(float* d, const u32* a, const u32* b) {
    asm volatile("mma.sync.aligned.m16n8k16.row.col.f32.bf16.bf16.f32 "
                 "{%0,%1,%2,%3}, {%4,%5,%6,%7}, {%8,%9}, {%0,%1,%2,%3};"
                 : "+f"(d[0]), "+f"(d[1]), "+f"(d[2]), "+f"(d[3])
                 : "r"(a[0]), "r"(a[1]), "r"(a[2]), "r"(a[3]), "r"(b[0]), "r"(b[1]));
}
__device__ __forceinline__ void cpa(u32 s, const void* g) {
    asm volatile("cp.async.cg.shared.global [%0], [%1], 16;" :: "r"(s), "l"(g));
}
#define CPC()  asm volatile("cp.async.commit_group;" ::: "memory")
#define CPW2() asm volatile("cp.async.wait_group 2;" ::: "memory")
#define CPW1() asm volatile("cp.async.wait_group 1;" ::: "memory")
#define CPW0() asm volatile("cp.async.wait_group 0;" ::: "memory")

__device__ __forceinline__ u32 pack_bf(bf16 a, bf16 b) {
    return (u32)__bfloat16_as_ushort(a) | ((u32)__bfloat16_as_ushort(b) << 16);
}
__device__ __forceinline__ void bsplit(float v, bf16& h, bf16& l) {
    h = __float2bfloat16(v);
    l = __float2bfloat16(v - __bfloat162float(h));
}
__device__ __forceinline__ u32 pack_h(float a, float b) {
    bf16 h0, l0, h1, l1; bsplit(a, h0, l0); bsplit(b, h1, l1); return pack_bf(h0, h1);
}
__device__ __forceinline__ u32 pack_l(float a, float b) {
    bf16 h0, l0, h1, l1; bsplit(a, h0, l0); bsplit(b, h1, l1); return pack_bf(l0, l1);
}

// ===== 4-stage ring: stage = Ah@0 Al@6144 Bh@12288 Bl@18432, 24576B each =====
// tile: 128 rows x 16 bf16 cols, row stride 24 elems (48B) — ldsm bank-clean.
#define STG 24576
__device__ __forceinline__ void cp_t16(u32 dst, const bf16* __restrict__ src,
                                       int ld, int k0, int tid) {
    int row = tid >> 1, c = tid & 1;
    cpa(dst + (row * 24 + c * 8) * 2, &src[(long long)row * ld + k0 + c * 8]);
}
__device__ __forceinline__ void issue16(u32 sb, int st,
                                        const bf16* Ah, const bf16* Al,
                                        const bf16* Bh, const bf16* Bl,
                                        int lda, int ldb, int tid) {
    u32 b = sb + (st & 3) * STG;
    int k0 = st * 16;
    cp_t16(b, Ah, lda, k0, tid);
    cp_t16(b + 6144, Al, lda, k0, tid);
    cp_t16(b + 12288, Bh, ldb, k0, tid);
    cp_t16(b + 18432, Bl, ldb, k0, tid);
    CPC();
}
// warp tile 32(m) x 64(n), k=16; acc += AhBh + AhBl + AlBh
__device__ __forceinline__ void wchunk16(float c[2][8][4], u32 base, int lane, int wy, int wx) {
    int rowA = wy * 32 + (lane & 15);
    int colA = (lane >> 4) * 8;
    int rowB = wx * 64 + (lane & 7) + ((lane >> 4) << 3);
    int colB = ((lane >> 3) & 1) * 8;
    u32 ah[2][4], al[2][4], bh[4][4], bl[4][4];
#pragma unroll
    for (int mi = 0; mi < 2; mi++) {
        u32 ao = ((rowA + mi * 16) * 24 + colA) * 2;
        ldsm4(ah[mi], base + ao);
        ldsm4(al[mi], base + 6144 + ao);
    }
#pragma unroll
    for (int np = 0; np < 4; np++) {
        u32 bo = ((rowB + np * 16) * 24 + colB) * 2;
        ldsm4(bh[np], base + 12288 + bo);
        ldsm4(bl[np], base + 18432 + bo);
    }
#pragma unroll
    for (int mi = 0; mi < 2; mi++)
#pragma unroll
        for (int ni = 0; ni < 8; ni++)
            mmabf(c[mi][ni], ah[mi], &bh[ni >> 1][(ni & 1) * 2]);
#pragma unroll
    for (int mi = 0; mi < 2; mi++)
#pragma unroll
        for (int ni = 0; ni < 8; ni++)
            mmabf(c[mi][ni], ah[mi], &bl[ni >> 1][(ni & 1) * 2]);
#pragma unroll
    for (int mi = 0; mi < 2; mi++)
#pragma unroll
        for (int ni = 0; ni < 8; ni++)
            mmabf(c[mi][ni], al[mi], &bh[ni >> 1][(ni & 1) * 2]);
}
template <int NCH>
__device__ __forceinline__ void gmain4(const bf16* Ah, const bf16* Al,
                                       const bf16* Bh, const bf16* Bl,
                                       int lda, int ldb, float c[2][8][4],
                                       u32 sb, int tid, int lane, int wy, int wx) {
    issue16(sb, 0, Ah, Al, Bh, Bl, lda, ldb, tid);
    issue16(sb, 1, Ah, Al, Bh, Bl, lda, ldb, tid);
    issue16(sb, 2, Ah, Al, Bh, Bl, lda, ldb, tid);
    for (int ch = 0; ch < NCH; ch++) {
        if (ch < NCH - 2) { CPW2(); } else if (ch == NCH - 2) { CPW1(); } else { CPW0(); }
        __syncthreads();
        wchunk16(c, sb + (ch & 3) * STG, lane, wy, wx);
        if (ch + 3 < NCH)
            issue16(sb, ch + 3, Ah, Al, Bh, Bl, lda, ldb, tid);
    }
}

// ---------------- K0: split trig tables ----------------
__global__ void k_tables() {
    int a = blockIdx.x, b = threadIdx.x;
    int s = b & 63, k = s - 32;
    int q = ((k * a) % 256 + 256) % 256;
    float sv, cv;
    sincospif((float)q * (1.0f / 128.0f), &sv, &cv);
    float tc = (b < 64) ? cv : sv;
    bf16 h, l;
    bsplit(tc, h, l);
    g_Tch[b * 256 + a] = h; g_Tcl[b * 256 + a] = l;
    g_T5h[a * 128 + b] = h; g_T5l[a * 128 + b] = l;
    int c = b >> 6;
    float a5 = c ? (cv - sv) : (cv + sv);
    bsplit(a5, h, l);
    g_A5h[(c * 256 + a) * 64 + s] = h;
    g_A5l[(c * 256 + a) * 64 + s] = l;
}

// ---------------- Kw: weight transpose ----------------
__global__ void k_wt(const float* __restrict__ w) {
    __shared__ float tile[32][33];
    int x0 = blockIdx.x * 32, y0 = blockIdx.y * 32;
    int tx = threadIdx.x, ty = threadIdx.y;
#pragma unroll
    for (int r = 0; r < 32; r += 8)
        tile[ty + r][tx] = w[(y0 + ty + r) * 4096 + x0 + tx];
    __syncthreads();
#pragma unroll
    for (int r = 0; r < 32; r += 8)
        g_Wt[(x0 + ty + r) * 4096 + y0 + tx] = tile[tx][ty + r];
}

// ---------------- K1: 4-stage ring; tables cp.async, x LDG+split ----------------
__global__ __launch_bounds__(256, 2) void k1_fwd(const float* __restrict__ x) {
    extern __shared__ char smem[];
    u32 sb = smem_u32(smem);
    int tid = threadIdx.x, lane = tid & 31, w = tid >> 5, wy = w >> 1, wx = w & 1;
    int mt = blockIdx.x, img = mt >> 1, mh = mt & 1;
    const float* xb = x + (long long)mt * 128 * 256;
    const int xrow = tid >> 1, xseg = tid & 1;   // 128 rows x 2 segs of 8 floats
    float c[2][8][4];
#pragma unroll
    for (int i = 0; i < 2; i++)
#pragma unroll
        for (int j = 0; j < 8; j++)
#pragma unroll
            for (int r = 0; r < 4; r++) c[i][j][r] = 0.f;

    // prologue: table chunks 0..2 (3 commit groups), x chunks 0..2 split->smem
#pragma unroll
    for (int st = 0; st < 3; st++) {
        u32 b = sb + st * STG;
        cp_t16(b, g_Tch, 256, st * 16, tid);
        cp_t16(b + 6144, g_Tcl, 256, st * 16, tid);
        CPC();
        const float* s = &xb[xrow * 256 + st * 16 + xseg * 8];
        float4 v0 = *(const float4*)s, v1 = *(const float4*)(s + 4);
        u32 hh[4] = {pack_h(v0.x, v0.y), pack_h(v0.z, v0.w), pack_h(v1.x, v1.y), pack_h(v1.z, v1.w)};
        u32 ll[4] = {pack_l(v0.x, v0.y), pack_l(v0.z, v0.w), pack_l(v1.x, v1.y), pack_l(v1.z, v1.w)};
        int off = (xrow * 24 + xseg * 8) * 2;
        *(uint4*)(smem + st * STG + 12288 + off) = *(uint4*)hh;
        *(uint4*)(smem + st * STG + 18432 + off) = *(uint4*)ll;
    }
    const int NCH = 16;
    for (int ch = 0; ch < NCH; ch++) {
        if (ch < NCH - 2) { CPW2(); } else if (ch == NCH - 2) { CPW1(); } else { CPW0(); }
        __syncthreads();
        float4 v0, v1;
        bool pre = (ch + 3 < NCH);
        if (pre) {
            const float* s = &xb[xrow * 256 + (ch + 3) * 16 + xseg * 8];
            v0 = *(const float4*)s; v1 = *(const float4*)(s + 4);   // LDG early
            u32 b = sb + ((ch + 3) & 3) * STG;
            cp_t16(b, g_Tch, 256, (ch + 3) * 16, tid);
            cp_t16(b + 6144, g_Tcl, 256, (ch + 3) * 16, tid);
            CPC();
        }
        wchunk16(c, sb + (ch & 3) * STG, lane, wy, wx);
        if (pre) {
            u32 hh[4] = {pack_h(v0.x, v0.y), pack_h(v0.z, v0.w), pack_h(v1.x, v1.y), pack_h(v1.z, v1.w)};
            u32 ll[4] = {pack_l(v0.x, v0.y), pack_l(v0.z, v0.w), pack_l(v1.x, v1.y), pack_l(v1.z, v1.w)};
            int off = (xrow * 24 + xseg * 8) * 2;
            *(uint4*)(smem + ((ch + 3) & 3) * STG + 12288 + off) = *(uint4*)hh;
            *(uint4*)(smem + ((ch + 3) & 3) * STG + 18432 + off) = *(uint4*)ll;
        }
    }
    int g = lane >> 2, cp = (lane & 3) * 2;
#pragma unroll
    for (int mi = 0; mi < 2; mi++)
#pragma unroll
        for (int ni = 0; ni < 8; ni++) {
            int col = mh * 128 + wx * 64 + ni * 8 + cp;
            int r0 = wy * 32 + mi * 16 + g;
            int b0 = (img * 128 + r0) * 256 + col;
            int b1 = b0 + 8 * 256;
            float* d = c[mi][ni];
            *(u32*)&g_Uth[b0] = pack_h(d[0], d[1]);
            *(u32*)&g_Utl[b0] = pack_l(d[0], d[1]);
            *(u32*)&g_Uth[b1] = pack_h(d[2], d[3]);
            *(u32*)&g_Utl[b1] = pack_l(d[2], d[3]);
        }
}

// ---------------- K2 ----------------
__global__ __launch_bounds__(256, 2) void k2_fwd() {
    extern __shared__ char smem[];
    u32 sb = smem_u32(smem);
    int tid = threadIdx.x, lane = tid & 31, w = tid >> 5, wy = w >> 1, wx = w & 1;
    int img = blockIdx.x;
    float c[2][8][4];
#pragma unroll
    for (int i = 0; i < 2; i++)
#pragma unroll
        for (int j = 0; j < 8; j++)
#pragma unroll
            for (int r = 0; r < 4; r++) c[i][j][r] = 0.f;
    gmain4<16>(g_Tch, g_Tcl, g_Uth + img * 32768, g_Utl + img * 32768,
               256, 256, c, sb, tid, lane, wy, wx);
    __syncthreads();
    float* F = (float*)smem;  // [128][132]
    int g = lane >> 2, cp = (lane & 3) * 2;
#pragma unroll
    for (int mi = 0; mi < 2; mi++)
#pragma unroll
        for (int ni = 0; ni < 8; ni++) {
            int col = wx * 64 + ni * 8 + cp;
            int r0 = wy * 32 + mi * 16 + g;
            float* d = c[mi][ni];
            F[r0 * 132 + col] = d[0];
            F[r0 * 132 + col + 1] = d[1];
            F[(r0 + 8) * 132 + col] = d[2];
            F[(r0 + 8) * 132 + col + 1] = d[3];
        }
    __syncthreads();
    const int b = img >> 6, ic = img & 63;
#pragma unroll
    for (int t = 0; t < 16; t++) {
        int p = tid + t * 256;
        int s1 = p >> 6, s2 = p & 63;
        float r00 = F[s1 * 132 + s2];
        float r01 = F[s1 * 132 + 64 + s2];
        float r10 = F[(64 + s1) * 132 + s2];
        float r11 = F[(64 + s1) * 132 + 64 + s2];
        int a = p * 1024 + ic * 16 + b;
        g_CS[a] = r00 - r11;
        g_CS[4194304 + a] = r10 + r01;
    }
}

// ---------------- K3: channel mixing (fp32) ----------------
__device__ __forceinline__ ull pk2(float lo, float hi) {
    ull r; asm("mov.b64 %0, {%1, %2};" : "=l"(r) : "f"(lo), "f"(hi)); return r;
}
__device__ __forceinline__ float2 up2(ull v) {
    float2 f; asm("mov.b64 {%0, %1}, %2;" : "=f"(f.x), "=f"(f.y) : "l"(v)); return f;
}
__device__ __forceinline__ void fm2(ull& d, ull a, ull b) {
    asm("fma.rn.f32x2 %0, %1, %2, %0;" : "+l"(d) : "l"(a), "l"(b));
}
__global__ __launch_bounds__(256) void k_mix() {
    __shared__ float sC[1024], sS[1024];
    __shared__ float sW[4096], sWr[4096];
    const int mode = blockIdx.x;
    const int s1 = mode >> 6, s2 = mode & 63;
    const int f1 = (64 - s1) & 63, f2 = (64 - s2) & 63;
    const int tid = threadIdx.x;
    for (int t = tid; t < 1024; t += 256) {
        sC[t] = g_CS[mode * 1024 + t];
        sS[t] = g_CS[4194304 + mode * 1024 + t];
    }
    for (int t = tid; t < 4096; t += 256) {
        sW[t] = g_Wt[mode * 4096 + t];
        sWr[t] = g_Wt[(f1 * 64 + f2) * 4096 + t];
    }
    __syncthreads();
    const int o = tid & 63, bq = tid >> 6;
    ull acc01 = 0ull, acc23 = 0ull;
#pragma unroll 8
    for (int i = 0; i < 64; i++) {
        float wv = sW[i * 64 + o];
        float wr = sWr[i * 64 + o];
        ull ww = pk2(wv, wv), wwr = pk2(wr, wr);
        fm2(acc01, *(const ull*)&sC[i * 16 + bq * 4], ww);
        fm2(acc01, *(const ull*)&sS[i * 16 + bq * 4], wwr);
        fm2(acc23, *(const ull*)&sC[i * 16 + bq * 4 + 2], ww);
        fm2(acc23, *(const ull*)&sS[i * 16 + bq * 4 + 2], wwr);
    }
    float2 v01 = up2(acc01), v23 = up2(acc23);
    float vals[4] = {v01.x, v01.y, v23.x, v23.y};
#pragma unroll
    for (int r = 0; r < 4; r++) {
        int img2 = (bq * 4 + r) * 64 + o;
        bf16 h, l;
        bsplit(vals[r], h, l);
        g_Tth[img2 * 4096 + s2 * 64 + s1] = h;
        g_Ttl[img2 * 4096 + s2 * 64 + s1] = l;
    }
}

// ---------------- K4: M=256(c,m), N=64, K=64, 3 segs, cp.async ----------------
__device__ __forceinline__ void k4_issue(u32 sb, int bufo, const bf16* __restrict__ A,
                                         const bf16* __restrict__ B, int m0, int k0, int tid) {
#pragma unroll
    for (int t = 0; t < 4; t++) {
        int f = tid + t * 256, row = f >> 2, cc = f & 3;
        int gr = (row < 128) ? (m0 + row) : (256 + m0 + row - 128);
        cpa(sb + bufo + (row * 40 + cc * 8) * 2, &A[gr * 64 + k0 + cc * 8]);
    }
    {
        int row = tid >> 2, cc = tid & 3;
        cpa(sb + bufo + 20480 + (row * 40 + cc * 8) * 2, &B[row * 64 + k0 + cc * 8]);
    }
    CPC();
}
__global__ __launch_bounds__(256, 2) void k4_inv() {
    extern __shared__ char smem[];
    u32 sb = smem_u32(smem);
    int tid = threadIdx.x, lane = tid & 31, w = tid >> 5, wy = w >> 1, wx = w & 1;
    int img = blockIdx.x >> 1, m0 = (blockIdx.x & 1) * 128;
    const bf16* As[3] = {g_A5h, g_A5h, g_A5l};
    const bf16* Bs[3] = {g_Tth + img * 4096, g_Ttl + img * 4096, g_Tth + img * 4096};
    const int BUF = 25600;
    float c[4][4][4];
#pragma unroll
    for (int i = 0; i < 4; i++)
#pragma unroll
        for (int j = 0; j < 4; j++)
#pragma unroll
            for (int r = 0; r < 4; r++) c[i][j][r] = 0.f;
    k4_issue(sb, 0, As[0], Bs[0], m0, 0, tid);
    k4_issue(sb, BUF, As[0], Bs[0], m0, 32, tid);
    const int NCH = 6;
    for (int ch = 0; ch < NCH; ch++) {
        if (ch + 1 < NCH) { CPW1(); } else { CPW0(); }
        __syncthreads();
        {
            u32 sA = sb + (ch & 1) * BUF, sB = sA + 20480;
            int rowA = wy * 64 + (lane & 15);
            int colA = (lane >> 4) * 8;
            int rowB = wx * 32 + (lane & 7) + ((lane >> 4) << 3);
            int colB = ((lane >> 3) & 1) * 8;
#pragma unroll
            for (int kk = 0; kk < 32; kk += 16) {
                u32 a[4][4], b[2][4];
#pragma unroll
                for (int mi = 0; mi < 4; mi++)
                    ldsm4(a[mi], sA + ((rowA + mi * 16) * 40 + kk + colA) * 2);
#pragma unroll
                for (int np = 0; np < 2; np++)
                    ldsm4(b[np], sB + ((rowB + np * 16) * 40 + kk + colB) * 2);
#pragma unroll
                for (int mi = 0; mi < 4; mi++)
#pragma unroll
                    for (int ni = 0; ni < 4; ni++)
                        mmabf(c[mi][ni], a[mi], &b[ni >> 1][(ni & 1) * 2]);
            }
        }
        if (ch + 2 < NCH) {
            __syncthreads();
            int seg = (ch + 2) / 2, k0 = ((ch + 2) % 2) * 32;
            k4_issue(sb, (ch & 1) * BUF, As[seg], Bs[seg], m0, k0, tid);
        }
    }
    int g = lane >> 2, cp = (lane & 3) * 2;
#pragma unroll
    for (int mi = 0; mi < 4; mi++)
#pragma unroll
        for (int ni = 0; ni < 4; ni++) {
            int s2 = wx * 32 + ni * 8 + cp;
            float* d = c[mi][ni];
#pragma unroll
            for (int half = 0; half < 2; half++) {
                int rL = wy * 64 + mi * 16 + g + half * 8;
                int cc = rL >> 7, m = m0 + (rL & 127);
                int idx = (img * 256 + m) * 128 + cc * 64 + s2;
                *(u32*)&g_Wh[idx] = pack_h(d[half * 2], d[half * 2 + 1]);
                *(u32*)&g_Wl[idx] = pack_l(d[half * 2], d[half * 2 + 1]);
            }
        }
}

// ---------------- K5 ----------------
__global__ __launch_bounds__(256, 2) void k5_inv(const float* __restrict__ bias,
                                                 float* __restrict__ out) {
    extern __shared__ char smem[];
    u32 sb = smem_u32(smem);
    int tid = threadIdx.x, lane = tid & 31, w = tid >> 5, wy = w >> 1, wx = w & 1;
    int n0 = blockIdx.x * 128, m0 = blockIdx.y * 128, img = blockIdx.z;
    float c[2][8][4];
#pragma unroll
    for (int i = 0; i < 2; i++)
#pragma unroll
        for (int j = 0; j < 8; j++)
#pragma unroll
            for (int r = 0; r < 4; r++) c[i][j][r] = 0.f;
    gmain4<8>(g_Wh + (img * 256 + m0) * 128, g_Wl + (img * 256 + m0) * 128,
              g_T5h + n0 * 128, g_T5l + n0 * 128,
              128, 128, c, sb, tid, lane, wy, wx);
    const float bv = bias[img & 63];
    const float sc = 1.0f / 65536.0f;
    int g = lane >> 2, cp = (lane & 3) * 2;
#pragma unroll
    for (int mi = 0; mi < 2; mi++)
#pragma unroll
        for (int ni = 0; ni < 8; ni++) {
            int col = n0 + wx * 64 + ni * 8 + cp;
            float* d = c[mi][ni];
#pragma unroll
            for (int half = 0; half < 2; half++) {
                int m = m0 + wy * 32 + mi * 16 + g + half * 8;
                float2 v;
                v.x = fmaxf(fmaf(d[half * 2], sc, bv), 0.f);
                v.y = fmaxf(fmaf(d[half * 2 + 1], sc, bv), 0.f);
                *(float2*)&out[(img * 256 + m) * 256 + col] = v;
            }
        }
}

extern "C" void kernel_launch(void* const* d_in, const int* in_sizes, int n_in,
                              void* d_out, int out_size) {
    const float* x = (const float*)d_in[0];
    const float* wgt = (const float*)d_in[1];
    const float* bias = (const float*)d_in[2];
    float* out = (float*)d_out;

    cudaFuncSetAttribute(k1_fwd, cudaFuncAttributeMaxDynamicSharedMemorySize, 98304);
    cudaFuncSetAttribute(k2_fwd, cudaFuncAttributeMaxDynamicSharedMemorySize, 98304);
    cudaFuncSetAttribute(k4_inv, cudaFuncAttributeMaxDynamicSharedMemorySize, 51200);
    cudaFuncSetAttribute(k5_inv, cudaFuncAttributeMaxDynamicSharedMemorySize, 98304);

    k_tables<<<256, 128>>>();
    k_wt<<<dim3(128, 128), dim3(32, 8)>>>(wgt);
    k1_fwd<<<2048, 256, 98304>>>(x);
    k2_fwd<<<1024, 256, 98304>>>();
    k_mix<<<4096, 256>>>();
    k4_inv<<<2048, 256, 51200>>>();
    k5_inv<<<dim3(2, 2, 1024), 256, 98304>>>(bias, out);
}

// round 10
// speedup vs baseline: 1.1016x; 1.1016x over previous
#include <cuda_runtime.h>
#include <cuda_bf16.h>
#include <cstdint>

// HartleySpectralConv2d B=16,CI=CO=64,H=W=256, modes 64x64.
// Split-bf16 GEMMs on mma.sync.m16n8k16; 3-stage cp.async ring (k=32 chunks),
// XOR-swizzled 8KB tiles, one barrier per chunk, 2 CTA/SM.

using bf16 = __nv_bfloat16;
using u32 = uint32_t; using ull = unsigned long long;

__device__ bf16 g_Tch[128 * 256], g_Tcl[128 * 256];       // [j][n] K-major
__device__ bf16 g_A5h[2 * 256 * 64], g_A5l[2 * 256 * 64]; // [(c*256+m)][s1]
__device__ bf16 g_T5h[256 * 128], g_T5l[256 * 128];       // [n][c*64+s2]
__device__ bf16 g_Uth[1024 * 128 * 256], g_Utl[1024 * 128 * 256]; // [img][j][m]
__device__ float g_Wt[4096 * 4096];                       // [mode][i*64+o]
__device__ float g_CS[2 * 4096 * 1024];                   // [comp][mode][ci*16+b]
__device__ bf16 g_Tth[1024 * 4096], g_Ttl[1024 * 4096];   // [img][s2*64+s1]
__device__ bf16 g_Wh[1024 * 256 * 128], g_Wl[1024 * 256 * 128]; // [img][m][k]

// ---------------- helpers ----------------
__device__ __forceinline__ u32 smem_u32(const void* p) {
    u32 a;
    asm("{ .reg .u64 t; cvta.to.shared.u64 t, %1; cvt.u32.u64 %0, t; }" : "=r"(a) : "l"(p));
    return a;
}
__device__ __forceinline__ void ldsm4(u32* r, u32 a) {
    asm volatile("ldmatrix.sync.aligned.m8n8.x4.shared.b16 {%0,%1,%2,%3}, [%4];"
                 : "=r"(r[0]), "=r"(r[1]), "=r"(r[2]), "=r"(r[3]) : "r"(a));
}
__device__ __forceinline__ void mmabf(float* d, const u32* a, const u32* b) {
    asm volatile("mma.sync.aligned.m16n8k16.row.col.f32.bf16.bf16.f32 "
                 "{%0,%1,%2,%3}, {%4,%5,%6,%7}, {%8,%9}, {%0,%1,%2,%3};"
                 : "+f"(d[0]), "+f"(d[1]), "+f"(d[2]), "+f"(d[3])
                 : "r"(a[0]), "r"(a[1]), "r"(a[2]), "r"(a[3]), "r"(b[0]), "r"(b[1]));
}
__device__ __forceinline__ void cpa(u32 s, const void* g) {
    asm volatile("cp.async.cg.shared.global [%0], [%1], 16;" :: "r"(s), "l"(g));
}
#define CPC()  asm volatile("cp.async.commit_group;" ::: "memory")
#define CPW1() asm volatile("cp.async.wait_group 1;" ::: "memory")
#define CPW0() asm volatile("cp.async.wait_group 0;" ::: "memory")

__device__ __forceinline__ u32 pack_bf(bf16 a, bf16 b) {
    return (u32)__bfloat16_as_ushort(a) | ((u32)__bfloat16_as_ushort(b) << 16);
}
__device__ __forceinline__ void bsplit(float v, bf16& h, bf16& l) {
    h = __float2bfloat16(v);
    l = __float2bfloat16(v - __bfloat162float(h));
}
__device__ __forceinline__ u32 pack_h(float a, float b) {
    bf16 h0, l0, h1, l1; bsplit(a, h0, l0); bsplit(b, h1, l1); return pack_bf(h0, h1);
}
__device__ __forceinline__ u32 pack_l(float a, float b) {
    bf16 h0, l0, h1, l1; bsplit(a, h0, l0); bsplit(b, h1, l1); return pack_bf(l0, l1);
}

// ===== swizzled 8KB tile: 128 rows x 32 bf16 (64B/row), 4 chunks of 16B =====
// addr = row*64 + (chunk ^ ((row>>1)&3))*16  — all 8 rows of an ldsm phase
// hit distinct 16B bank-groups for any chunk.
__device__ __forceinline__ u32 SWZ(int row, int chunk) {
    return (u32)(row * 64 + ((chunk ^ ((row >> 1) & 3)) << 4));
}
// ===== 3-stage ring: stage = Ah@0 Al@8192 Bh@16384 Bl@24576 (32768B) =====
#define STG 32768
__device__ __forceinline__ void cp_tile32(u32 dst, const bf16* __restrict__ src,
                                          int ld, int k0, int tid) {
#pragma unroll
    for (int t = 0; t < 2; t++) {
        int f = tid + t * 256, row = f >> 2, c = f & 3;
        cpa(dst + SWZ(row, c), &src[(long long)row * ld + k0 + c * 8]);
    }
}
__device__ __forceinline__ void issue32(u32 sb, int st,
                                        const bf16* Ah, const bf16* Al,
                                        const bf16* Bh, const bf16* Bl,
                                        int lda, int ldb, int tid) {
    u32 b = sb + (st % 3) * STG;
    int k0 = st * 32;
    cp_tile32(b, Ah, lda, k0, tid);
    cp_tile32(b + 8192, Al, lda, k0, tid);
    cp_tile32(b + 16384, Bh, ldb, k0, tid);
    cp_tile32(b + 24576, Bl, ldb, k0, tid);
    CPC();
}
// warp tile 32(m) x 64(n), k=32; acc += AhBh + AhBl + AlBh
__device__ __forceinline__ void wchunk32(float c[2][8][4], u32 base, int lane, int wy, int wx) {
    int rA = wy * 32 + (lane & 15);
    int cA = lane >> 4;                       // chunk 0/1 within k-half
    int rB = wx * 64 + (lane & 7) + ((lane >> 4) << 3);
    int cB = (lane >> 3) & 1;
#pragma unroll
    for (int kk = 0; kk < 2; kk++) {          // k-halves, chunk base 0/2
        int kc = kk * 2;
        u32 ah[2][4], al[2][4], bh[4][4], bl[4][4];
#pragma unroll
        for (int mi = 0; mi < 2; mi++) {
            u32 ao = SWZ(rA + mi * 16, kc + cA);
            ldsm4(ah[mi], base + ao);
            ldsm4(al[mi], base + 8192 + ao);
        }
#pragma unroll
        for (int np = 0; np < 4; np++) {
            u32 bo = SWZ(rB + np * 16, kc + cB);
            ldsm4(bh[np], base + 16384 + bo);
            ldsm4(bl[np], base + 24576 + bo);
        }
#pragma unroll
        for (int mi = 0; mi < 2; mi++)
#pragma unroll
            for (int ni = 0; ni < 8; ni++)
                mmabf(c[mi][ni], ah[mi], &bh[ni >> 1][(ni & 1) * 2]);
#pragma unroll
        for (int mi = 0; mi < 2; mi++)
#pragma unroll
            for (int ni = 0; ni < 8; ni++)
                mmabf(c[mi][ni], ah[mi], &bl[ni >> 1][(ni & 1) * 2]);
#pragma unroll
        for (int mi = 0; mi < 2; mi++)
#pragma unroll
            for (int ni = 0; ni < 8; ni++)
                mmabf(c[mi][ni], al[mi], &bh[ni >> 1][(ni & 1) * 2]);
    }
}
template <int NCH>
__device__ __forceinline__ void gmain3(const bf16* Ah, const bf16* Al,
                                       const bf16* Bh, const bf16* Bl,
                                       int lda, int ldb, float c[2][8][4],
                                       u32 sb, int tid, int lane, int wy, int wx) {
    issue32(sb, 0, Ah, Al, Bh, Bl, lda, ldb, tid);
    issue32(sb, 1, Ah, Al, Bh, Bl, lda, ldb, tid);
    for (int ch = 0; ch < NCH; ch++) {
        if (ch + 1 < NCH) { CPW1(); } else { CPW0(); }
        __syncthreads();
        if (ch + 2 < NCH)
            issue32(sb, ch + 2, Ah, Al, Bh, Bl, lda, ldb, tid);
        wchunk32(c, sb + (ch % 3) * STG, lane, wy, wx);
    }
}

// ---------------- K0: split trig tables ----------------
__global__ void k_tables() {
    int a = blockIdx.x, b = threadIdx.x;
    int s = b & 63, k = s - 32;
    int q = ((k * a) % 256 + 256) % 256;
    float sv, cv;
    sincospif((float)q * (1.0f / 128.0f), &sv, &cv);
    float tc = (b < 64) ? cv : sv;
    bf16 h, l;
    bsplit(tc, h, l);
    g_Tch[b * 256 + a] = h; g_Tcl[b * 256 + a] = l;
    g_T5h[a * 128 + b] = h; g_T5l[a * 128 + b] = l;
    int c = b >> 6;
    float a5 = c ? (cv - sv) : (cv + sv);
    bsplit(a5, h, l);
    g_A5h[(c * 256 + a) * 64 + s] = h;
    g_A5l[(c * 256 + a) * 64 + s] = l;
}

// ---------------- Kw: weight transpose ----------------
__global__ void k_wt(const float* __restrict__ w) {
    __shared__ float tile[32][33];
    int x0 = blockIdx.x * 32, y0 = blockIdx.y * 32;
    int tx = threadIdx.x, ty = threadIdx.y;
#pragma unroll
    for (int r = 0; r < 32; r += 8)
        tile[ty + r][tx] = w[(y0 + ty + r) * 4096 + x0 + tx];
    __syncthreads();
#pragma unroll
    for (int r = 0; r < 32; r += 8)
        g_Wt[(x0 + ty + r) * 4096 + y0 + tx] = tile[tx][ty + r];
}

// ---------------- K1: tables via cp.async ring; x LDG+split ----------------
__global__ __launch_bounds__(256, 2) void k1_fwd(const float* __restrict__ x) {
    extern __shared__ char smem[];
    u32 sb = smem_u32(smem);
    int tid = threadIdx.x, lane = tid & 31, w = tid >> 5, wy = w >> 1, wx = w & 1;
    int mt = blockIdx.x, img = mt >> 1, mh = mt & 1;
    const float* xb = x + (long long)mt * 128 * 256;
    const int xrow = tid >> 1, xhalf = tid & 1;   // 128 rows x 2 halves of 16 floats
    float c[2][8][4];
#pragma unroll
    for (int i = 0; i < 2; i++)
#pragma unroll
        for (int j = 0; j < 8; j++)
#pragma unroll
            for (int r = 0; r < 4; r++) c[i][j][r] = 0.f;

    // prologue: stages 0,1
#pragma unroll
    for (int st = 0; st < 2; st++) {
        u32 b = sb + st * STG;
        cp_tile32(b, g_Tch, 256, st * 32, tid);
        cp_tile32(b + 8192, g_Tcl, 256, st * 32, tid);
        CPC();
        const float* s = &xb[xrow * 256 + st * 32 + xhalf * 16];
        float4 v0 = *(const float4*)s, v1 = *(const float4*)(s + 4);
        float4 v2 = *(const float4*)(s + 8), v3 = *(const float4*)(s + 12);
        u32 h0[4] = {pack_h(v0.x, v0.y), pack_h(v0.z, v0.w), pack_h(v1.x, v1.y), pack_h(v1.z, v1.w)};
        u32 l0[4] = {pack_l(v0.x, v0.y), pack_l(v0.z, v0.w), pack_l(v1.x, v1.y), pack_l(v1.z, v1.w)};
        u32 h1[4] = {pack_h(v2.x, v2.y), pack_h(v2.z, v2.w), pack_h(v3.x, v3.y), pack_h(v3.z, v3.w)};
        u32 l1[4] = {pack_l(v2.x, v2.y), pack_l(v2.z, v2.w), pack_l(v3.x, v3.y), pack_l(v3.z, v3.w)};
        int c0 = xhalf * 2;
        *(uint4*)(smem + st * STG + 16384 + SWZ(xrow, c0)) = *(uint4*)h0;
        *(uint4*)(smem + st * STG + 16384 + SWZ(xrow, c0 + 1)) = *(uint4*)h1;
        *(uint4*)(smem + st * STG + 24576 + SWZ(xrow, c0)) = *(uint4*)l0;
        *(uint4*)(smem + st * STG + 24576 + SWZ(xrow, c0 + 1)) = *(uint4*)l1;
    }
    const int NCH = 8;
    for (int ch = 0; ch < NCH; ch++) {
        if (ch + 1 < NCH) { CPW1(); } else { CPW0(); }
        __syncthreads();
        bool pre = (ch + 2 < NCH);
        float4 v0, v1, v2, v3;
        if (pre) {
            const float* s = &xb[xrow * 256 + (ch + 2) * 32 + xhalf * 16];
            v0 = *(const float4*)s; v1 = *(const float4*)(s + 4);     // LDG early
            v2 = *(const float4*)(s + 8); v3 = *(const float4*)(s + 12);
            u32 b = sb + ((ch + 2) % 3) * STG;
            cp_tile32(b, g_Tch, 256, (ch + 2) * 32, tid);
            cp_tile32(b + 8192, g_Tcl, 256, (ch + 2) * 32, tid);
            CPC();
        }
        wchunk32(c, sb + (ch % 3) * STG, lane, wy, wx);
        if (pre) {
            u32 h0[4] = {pack_h(v0.x, v0.y), pack_h(v0.z, v0.w), pack_h(v1.x, v1.y), pack_h(v1.z, v1.w)};
            u32 l0[4] = {pack_l(v0.x, v0.y), pack_l(v0.z, v0.w), pack_l(v1.x, v1.y), pack_l(v1.z, v1.w)};
            u32 h1[4] = {pack_h(v2.x, v2.y), pack_h(v2.z, v2.w), pack_h(v3.x, v3.y), pack_h(v3.z, v3.w)};
            u32 l1[4] = {pack_l(v2.x, v2.y), pack_l(v2.z, v2.w), pack_l(v3.x, v3.y), pack_l(v3.z, v3.w)};
            u32 b = sb + ((ch + 2) % 3) * STG;
            int c0 = xhalf * 2;
            *(uint4*)(smem + (b - sb) + 16384 + SWZ(xrow, c0)) = *(uint4*)h0;
            *(uint4*)(smem + (b - sb) + 16384 + SWZ(xrow, c0 + 1)) = *(uint4*)h1;
            *(uint4*)(smem + (b - sb) + 24576 + SWZ(xrow, c0)) = *(uint4*)l0;
            *(uint4*)(smem + (b - sb) + 24576 + SWZ(xrow, c0 + 1)) = *(uint4*)l1;
        }
    }
    int g = lane >> 2, cp = (lane & 3) * 2;
#pragma unroll
    for (int mi = 0; mi < 2; mi++)
#pragma unroll
        for (int ni = 0; ni < 8; ni++) {
            int col = mh * 128 + wx * 64 + ni * 8 + cp;
            int r0 = wy * 32 + mi * 16 + g;
            int b0 = (img * 128 + r0) * 256 + col;
            int b1 = b0 + 8 * 256;
            float* d = c[mi][ni];
            *(u32*)&g_Uth[b0] = pack_h(d[0], d[1]);
            *(u32*)&g_Utl[b0] = pack_l(d[0], d[1]);
            *(u32*)&g_Uth[b1] = pack_h(d[2], d[3]);
            *(u32*)&g_Utl[b1] = pack_l(d[2], d[3]);
        }
}

// ---------------- K2 ----------------
__global__ __launch_bounds__(256, 2) void k2_fwd() {
    extern __shared__ char smem[];
    u32 sb = smem_u32(smem);
    int tid = threadIdx.x, lane = tid & 31, w = tid >> 5, wy = w >> 1, wx = w & 1;
    int img = blockIdx.x;
    float c[2][8][4];
#pragma unroll
    for (int i = 0; i < 2; i++)
#pragma unroll
        for (int j = 0; j < 8; j++)
#pragma unroll
            for (int r = 0; r < 4; r++) c[i][j][r] = 0.f;
    gmain3<8>(g_Tch, g_Tcl, g_Uth + img * 32768, g_Utl + img * 32768,
              256, 256, c, sb, tid, lane, wy, wx);
    __syncthreads();
    float* F = (float*)smem;  // [128][132]
    int g = lane >> 2, cp = (lane & 3) * 2;
#pragma unroll
    for (int mi = 0; mi < 2; mi++)
#pragma unroll
        for (int ni = 0; ni < 8; ni++) {
            int col = wx * 64 + ni * 8 + cp;
            int r0 = wy * 32 + mi * 16 + g;
            float* d = c[mi][ni];
            F[r0 * 132 + col] = d[0];
            F[r0 * 132 + col + 1] = d[1];
            F[(r0 + 8) * 132 + col] = d[2];
            F[(r0 + 8) * 132 + col + 1] = d[3];
        }
    __syncthreads();
    const int b = img >> 6, ic = img & 63;
#pragma unroll
    for (int t = 0; t < 16; t++) {
        int p = tid + t * 256;
        int s1 = p >> 6, s2 = p & 63;
        float r00 = F[s1 * 132 + s2];
        float r01 = F[s1 * 132 + 64 + s2];
        float r10 = F[(64 + s1) * 132 + s2];
        float r11 = F[(64 + s1) * 132 + 64 + s2];
        int a = p * 1024 + ic * 16 + b;
        g_CS[a] = r00 - r11;
        g_CS[4194304 + a] = r10 + r01;
    }
}

// ---------------- K3: channel mixing (fp32) ----------------
__device__ __forceinline__ ull pk2(float lo, float hi) {
    ull r; asm("mov.b64 %0, {%1, %2};" : "=l"(r) : "f"(lo), "f"(hi)); return r;
}
__device__ __forceinline__ float2 up2(ull v) {
    float2 f; asm("mov.b64 {%0, %1}, %2;" : "=f"(f.x), "=f"(f.y) : "l"(v)); return f;
}
__device__ __forceinline__ void fm2(ull& d, ull a, ull b) {
    asm("fma.rn.f32x2 %0, %1, %2, %0;" : "+l"(d) : "l"(a), "l"(b));
}
__global__ __launch_bounds__(256) void k_mix() {
    __shared__ float sC[1024], sS[1024];
    __shared__ float sW[4096], sWr[4096];
    const int mode = blockIdx.x;
    const int s1 = mode >> 6, s2 = mode & 63;
    const int f1 = (64 - s1) & 63, f2 = (64 - s2) & 63;
    const int tid = threadIdx.x;
    for (int t = tid; t < 1024; t += 256) {
        sC[t] = g_CS[mode * 1024 + t];
        sS[t] = g_CS[4194304 + mode * 1024 + t];
    }
    for (int t = tid; t < 4096; t += 256) {
        sW[t] = g_Wt[mode * 4096 + t];
        sWr[t] = g_Wt[(f1 * 64 + f2) * 4096 + t];
    }
    __syncthreads();
    const int o = tid & 63, bq = tid >> 6;
    ull acc01 = 0ull, acc23 = 0ull;
#pragma unroll 8
    for (int i = 0; i < 64; i++) {
        float wv = sW[i * 64 + o];
        float wr = sWr[i * 64 + o];
        ull ww = pk2(wv, wv), wwr = pk2(wr, wr);
        fm2(acc01, *(const ull*)&sC[i * 16 + bq * 4], ww);
        fm2(acc01, *(const ull*)&sS[i * 16 + bq * 4], wwr);
        fm2(acc23, *(const ull*)&sC[i * 16 + bq * 4 + 2], ww);
        fm2(acc23, *(const ull*)&sS[i * 16 + bq * 4 + 2], wwr);
    }
    float2 v01 = up2(acc01), v23 = up2(acc23);
    float vals[4] = {v01.x, v01.y, v23.x, v23.y};
#pragma unroll
    for (int r = 0; r < 4; r++) {
        int img2 = (bq * 4 + r) * 64 + o;
        bf16 h, l;
        bsplit(vals[r], h, l);
        g_Tth[img2 * 4096 + s2 * 64 + s1] = h;
        g_Ttl[img2 * 4096 + s2 * 64 + s1] = l;
    }
}

// ---------------- K4: M=256(c,m), N=64, K=64, 3 segs, cp.async ----------------
__device__ __forceinline__ void k4_issue(u32 sb, int bufo, const bf16* __restrict__ A,
                                         const bf16* __restrict__ B, int m0, int k0, int tid) {
#pragma unroll
    for (int t = 0; t < 4; t++) {
        int f = tid + t * 256, row = f >> 2, cc = f & 3;
        int gr = (row < 128) ? (m0 + row) : (256 + m0 + row - 128);
        cpa(sb + bufo + (row * 40 + cc * 8) * 2, &A[gr * 64 + k0 + cc * 8]);
    }
    {
        int row = tid >> 2, cc = tid & 3;
        cpa(sb + bufo + 20480 + (row * 40 + cc * 8) * 2, &B[row * 64 + k0 + cc * 8]);
    }
    CPC();
}
__global__ __launch_bounds__(256, 2) void k4_inv() {
    extern __shared__ char smem[];
    u32 sb = smem_u32(smem);
    int tid = threadIdx.x, lane = tid & 31, w = tid >> 5, wy = w >> 1, wx = w & 1;
    int img = blockIdx.x >> 1, m0 = (blockIdx.x & 1) * 128;
    const bf16* As[3] = {g_A5h, g_A5h, g_A5l};
    const bf16* Bs[3] = {g_Tth + img * 4096, g_Ttl + img * 4096, g_Tth + img * 4096};
    const int BUF = 25600;
    float c[4][4][4];
#pragma unroll
    for (int i = 0; i < 4; i++)
#pragma unroll
        for (int j = 0; j < 4; j++)
#pragma unroll
            for (int r = 0; r < 4; r++) c[i][j][r] = 0.f;
    k4_issue(sb, 0, As[0], Bs[0], m0, 0, tid);
    k4_issue(sb, BUF, As[0], Bs[0], m0, 32, tid);
    const int NCH = 6;
    for (int ch = 0; ch < NCH; ch++) {
        if (ch + 1 < NCH) { CPW1(); } else { CPW0(); }
        __syncthreads();
        {
            u32 sA = sb + (ch & 1) * BUF, sB = sA + 20480;
            int rowA = wy * 64 + (lane & 15);
            int colA = (lane >> 4) * 8;
            int rowB = wx * 32 + (lane & 7) + ((lane >> 4) << 3);
            int colB = ((lane >> 3) & 1) * 8;
#pragma unroll
            for (int kk = 0; kk < 32; kk += 16) {
                u32 a[4][4], b[2][4];
#pragma unroll
                for (int mi = 0; mi < 4; mi++)
                    ldsm4(a[mi], sA + ((rowA + mi * 16) * 40 + kk + colA) * 2);
#pragma unroll
                for (int np = 0; np < 2; np++)
                    ldsm4(b[np], sB + ((rowB + np * 16) * 40 + kk + colB) * 2);
#pragma unroll
                for (int mi = 0; mi < 4; mi++)
#pragma unroll
                    for (int ni = 0; ni < 4; ni++)
                        mmabf(c[mi][ni], a[mi], &b[ni >> 1][(ni & 1) * 2]);
            }
        }
        if (ch + 2 < NCH) {
            __syncthreads();
            int seg = (ch + 2) / 2, k0 = ((ch + 2) % 2) * 32;
            k4_issue(sb, (ch & 1) * BUF, As[seg], Bs[seg], m0, k0, tid);
        }
    }
    int g = lane >> 2, cp = (lane & 3) * 2;
#pragma unroll
    for (int mi = 0; mi < 4; mi++)
#pragma unroll
        for (int ni = 0; ni < 4; ni++) {
            int s2 = wx * 32 + ni * 8 + cp;
            float* d = c[mi][ni];
#pragma unroll
            for (int half = 0; half < 2; half++) {
                int rL = wy * 64 + mi * 16 + g + half * 8;
                int cc = rL >> 7, m = m0 + (rL & 127);
                int idx = (img * 256 + m) * 128 + cc * 64 + s2;
                *(u32*)&g_Wh[idx] = pack_h(d[half * 2], d[half * 2 + 1]);
                *(u32*)&g_Wl[idx] = pack_l(d[half * 2], d[half * 2 + 1]);
            }
        }
}

// ---------------- K5 ----------------
__global__ __launch_bounds__(256, 2) void k5_inv(const float* __restrict__ bias,
                                                 float* __restrict__ out) {
    extern __shared__ char smem[];
    u32 sb = smem_u32(smem);
    int tid = threadIdx.x, lane = tid & 31, w = tid >> 5, wy = w >> 1, wx = w & 1;
    int n0 = blockIdx.x * 128, m0 = blockIdx.y * 128, img = blockIdx.z;
    float c[2][8][4];
#pragma unroll
    for (int i = 0; i < 2; i++)
#pragma unroll
        for (int j = 0; j < 8; j++)
#pragma unroll
            for (int r = 0; r < 4; r++) c[i][j][r] = 0.f;
    gmain3<4>(g_Wh + (img * 256 + m0) * 128, g_Wl + (img * 256 + m0) * 128,
              g_T5h + n0 * 128, g_T5l + n0 * 128,
              128, 128, c, sb, tid, lane, wy, wx);
    const float bv = bias[img & 63];
    const float sc = 1.0f / 65536.0f;
    int g = lane >> 2, cp = (lane & 3) * 2;
#pragma unroll
    for (int mi = 0; mi < 2; mi++)
#pragma unroll
        for (int ni = 0; ni < 8; ni++) {
            int col = n0 + wx * 64 + ni * 8 + cp;
            float* d = c[mi][ni];
#pragma unroll
            for (int half = 0; half < 2; half++) {
                int m = m0 + wy * 32 + mi * 16 + g + half * 8;
                float2 v;
                v.x = fmaxf(fmaf(d[half * 2], sc, bv), 0.f);
                v.y = fmaxf(fmaf(d[half * 2 + 1], sc, bv), 0.f);
                *(float2*)&out[(img * 256 + m) * 256 + col] = v;
            }
        }
}

extern "C" void kernel_launch(void* const* d_in, const int* in_sizes, int n_in,
                              void* d_out, int out_size) {
    const float* x = (const float*)d_in[0];
    const float* wgt = (const float*)d_in[1];
    const float* bias = (const float*)d_in[2];
    float* out = (float*)d_out;

    cudaFuncSetAttribute(k1_fwd, cudaFuncAttributeMaxDynamicSharedMemorySize, 98304);
    cudaFuncSetAttribute(k2_fwd, cudaFuncAttributeMaxDynamicSharedMemorySize, 98304);
    cudaFuncSetAttribute(k4_inv, cudaFuncAttributeMaxDynamicSharedMemorySize, 51200);
    cudaFuncSetAttribute(k5_inv, cudaFuncAttributeMaxDynamicSharedMemorySize, 98304);

    k_tables<<<256, 128>>>();
    k_wt<<<dim3(128, 128), dim3(32, 8)>>>(wgt);
    k1_fwd<<<2048, 256, 98304>>>(x);
    k2_fwd<<<1024, 256, 98304>>>();
    k_mix<<<4096, 256>>>();
    k4_inv<<<2048, 256, 51200>>>();
    k5_inv<<<dim3(2, 2, 1024), 256, 98304>>>(bias, out);
}

// round 11
// speedup vs baseline: 1.1613x; 1.0542x over previous
#include <cuda_runtime.h>
#include <cuda_bf16.h>
#include <cstdint>

// HartleySpectralConv2d B=16,CI=CO=64,H=W=256, modes 64x64.
// Split-bf16 HMMA GEMMs. R11: fuse K1+K2 and K4+K5 through smem-resident
// intermediates (eliminates ~800MB of HBM traffic). 512-thr CTAs, 1 per image.

using bf16 = __nv_bfloat16;
using u32 = uint32_t; using ull = unsigned long long;

__device__ bf16 g_Tch[128 * 256], g_Tcl[128 * 256];       // [j][a] K-major
__device__ bf16 g_A5h[2 * 256 * 64], g_A5l[2 * 256 * 64]; // [(c*256+m)][s1]
__device__ bf16 g_T5h[256 * 128], g_T5l[256 * 128];       // [n][c*64+s2]
__device__ float g_Wt[4096 * 4096];                       // [mode][i*64+o]
__device__ float g_CS[2 * 4096 * 1024];                   // [comp][mode][ci*16+b]
__device__ bf16 g_Tth[1024 * 4096], g_Ttl[1024 * 4096];   // [img][s2*64+s1]

// ---------------- helpers ----------------
__device__ __forceinline__ u32 smem_u32(const void* p) {
    u32 a;
    asm("{ .reg .u64 t; cvta.to.shared.u64 t, %1; cvt.u32.u64 %0, t; }" : "=r"(a) : "l"(p));
    return a;
}
__device__ __forceinline__ void ldsm4(u32* r, u32 a) {
    asm volatile("ldmatrix.sync.aligned.m8n8.x4.shared.b16 {%0,%1,%2,%3}, [%4];"
                 : "=r"(r[0]), "=r"(r[1]), "=r"(r[2]), "=r"(r[3]) : "r"(a));
}
__device__ __forceinline__ void mmabf(float* d, const u32* a, const u32* b) {
    asm volatile("mma.sync.aligned.m16n8k16.row.col.f32.bf16.bf16.f32 "
                 "{%0,%1,%2,%3}, {%4,%5,%6,%7}, {%8,%9}, {%0,%1,%2,%3};"
                 : "+f"(d[0]), "+f"(d[1]), "+f"(d[2]), "+f"(d[3])
                 : "r"(a[0]), "r"(a[1]), "r"(a[2]), "r"(a[3]), "r"(b[0]), "r"(b[1]));
}
__device__ __forceinline__ void cpa(u32 s, const void* g) {
    asm volatile("cp.async.cg.shared.global [%0], [%1], 16;" :: "r"(s), "l"(g));
}
#define CPC()  asm volatile("cp.async.commit_group;" ::: "memory")
#define CPW1() asm volatile("cp.async.wait_group 1;" ::: "memory")
#define CPW0() asm volatile("cp.async.wait_group 0;" ::: "memory")

__device__ __forceinline__ u32 pack_bf(bf16 a, bf16 b) {
    return (u32)__bfloat16_as_ushort(a) | ((u32)__bfloat16_as_ushort(b) << 16);
}
__device__ __forceinline__ void bsplit(float v, bf16& h, bf16& l) {
    h = __float2bfloat16(v);
    l = __float2bfloat16(v - __bfloat162float(h));
}
__device__ __forceinline__ u32 pack_h(float a, float b) {
    bf16 h0, l0, h1, l1; bsplit(a, h0, l0); bsplit(b, h1, l1); return pack_bf(h0, h1);
}
__device__ __forceinline__ u32 pack_l(float a, float b) {
    bf16 h0, l0, h1, l1; bsplit(a, h0, l0); bsplit(b, h1, l1); return pack_bf(l0, l1);
}

// swizzles (all verified conflict-free for 8-row ldsm phases)
__device__ __forceinline__ u32 SWZ(int row, int c) {           // 64B rows, c in [0,4)
    return (u32)(row * 64 + ((c ^ ((row >> 1) & 3)) << 4));
}
__device__ __forceinline__ u32 swzU(int j, int c16) {          // 512B rows, c16 in [0,32)
    return (u32)(j * 512 + ((((c16 ^ j) & 7) | (c16 & 24)) << 4));
}
__device__ __forceinline__ u32 swzW(int m, int c16) {          // 256B rows, c16 in [0,16)
    return (u32)(m * 256 + ((((c16 ^ m) & 7) | (c16 & 8)) << 4));
}
__device__ __forceinline__ u32 swzT(int r, int c16) {          // 128B rows, c16 in [0,8)
    return (u32)(r * 128 + ((c16 ^ (r & 7)) << 4));
}

// ---------------- K0: split trig tables ----------------
__global__ void k_tables() {
    int a = blockIdx.x, b = threadIdx.x;
    int s = b & 63, k = s - 32;
    int q = ((k * a) % 256 + 256) % 256;
    float sv, cv;
    sincospif((float)q * (1.0f / 128.0f), &sv, &cv);
    float tc = (b < 64) ? cv : sv;
    bf16 h, l;
    bsplit(tc, h, l);
    g_Tch[b * 256 + a] = h; g_Tcl[b * 256 + a] = l;
    g_T5h[a * 128 + b] = h; g_T5l[a * 128 + b] = l;
    int c = b >> 6;
    float a5 = c ? (cv - sv) : (cv + sv);
    bsplit(a5, h, l);
    g_A5h[(c * 256 + a) * 64 + s] = h;
    g_A5l[(c * 256 + a) * 64 + s] = l;
}

// ---------------- Kw: weight transpose ----------------
__global__ void k_wt(const float* __restrict__ w) {
    __shared__ float tile[32][33];
    int x0 = blockIdx.x * 32, y0 = blockIdx.y * 32;
    int tx = threadIdx.x, ty = threadIdx.y;
#pragma unroll
    for (int r = 0; r < 32; r += 8)
        tile[ty + r][tx] = w[(y0 + ty + r) * 4096 + x0 + tx];
    __syncthreads();
#pragma unroll
    for (int r = 0; r < 32; r += 8)
        g_Wt[(x0 + ty + r) * 4096 + y0 + tx] = tile[tx][ty + r];
}

// ---------------- K12: fused forward (per image) ----------------
// smem: Ut_h @0 (64K), Ut_l @65536 (64K), pipeline @131072 (96K)
__global__ __launch_bounds__(512, 1) void k12(const float* __restrict__ x) {
    extern __shared__ char smem[];
    u32 sb = smem_u32(smem);
    const int PIPE = 131072;
    int tid = threadIdx.x, lane = tid & 31, w = tid >> 5;
    int wy = w >> 2, wx = w & 3;        // 4x4 warp grid
    int img = blockIdx.x;
    int g = lane >> 2, cp2 = (lane & 3) * 2;
    int rA = wy * 32 + (lane & 15), cA = lane >> 4;
    int rB = wx * 32 + (lane & 7) + ((lane >> 4) << 3), cB = (lane >> 3) & 1;

    // ======== K1: two passes over m-halves ========
    for (int mh = 0; mh < 2; mh++) {
        const float* xb = x + (size_t)img * 65536 + mh * 128 * 256;
        const int xrow = tid >> 2, xq = tid & 3;
        float c[2][4][4];
#pragma unroll
        for (int i = 0; i < 2; i++)
#pragma unroll
            for (int j = 0; j < 4; j++)
#pragma unroll
                for (int r = 0; r < 4; r++) c[i][j][r] = 0.f;
        // prologue: stages 0,1 (tables cp.async; x direct split-store)
#pragma unroll
        for (int st = 0; st < 2; st++) {
            u32 b = sb + PIPE + st * 32768;
            cpa(b + SWZ(xrow, xq), &g_Tch[xrow * 256 + st * 32 + xq * 8]);
            cpa(b + 8192 + SWZ(xrow, xq), &g_Tcl[xrow * 256 + st * 32 + xq * 8]);
            CPC();
            const float* s = &xb[xrow * 256 + st * 32 + xq * 8];
            float4 v0 = *(const float4*)s, v1 = *(const float4*)(s + 4);
            u32 h4[4] = {pack_h(v0.x, v0.y), pack_h(v0.z, v0.w), pack_h(v1.x, v1.y), pack_h(v1.z, v1.w)};
            u32 l4[4] = {pack_l(v0.x, v0.y), pack_l(v0.z, v0.w), pack_l(v1.x, v1.y), pack_l(v1.z, v1.w)};
            *(uint4*)(smem + PIPE + st * 32768 + 16384 + SWZ(xrow, xq)) = *(uint4*)h4;
            *(uint4*)(smem + PIPE + st * 32768 + 24576 + SWZ(xrow, xq)) = *(uint4*)l4;
        }
        const int NCH = 8;
        for (int ch = 0; ch < NCH; ch++) {
            if (ch + 1 < NCH) { CPW1(); } else { CPW0(); }
            __syncthreads();
            bool pre = (ch + 2 < NCH);
            float4 v0, v1;
            if (pre) {
                const float* s = &xb[xrow * 256 + (ch + 2) * 32 + xq * 8];
                v0 = *(const float4*)s; v1 = *(const float4*)(s + 4);   // LDG early
                u32 b = sb + PIPE + ((ch + 2) % 3) * 32768;
                cpa(b + SWZ(xrow, xq), &g_Tch[xrow * 256 + (ch + 2) * 32 + xq * 8]);
                cpa(b + 8192 + SWZ(xrow, xq), &g_Tcl[xrow * 256 + (ch + 2) * 32 + xq * 8]);
                CPC();
            }
            u32 base = sb + PIPE + (ch % 3) * 32768;
#pragma unroll
            for (int kk = 0; kk < 2; kk++) {
                int kc = kk * 2;
                u32 ah[2][4], al[2][4], bh[2][4], bl[2][4];
#pragma unroll
                for (int mi = 0; mi < 2; mi++) {
                    u32 ao = SWZ(rA + mi * 16, kc + cA);
                    ldsm4(ah[mi], base + ao);
                    ldsm4(al[mi], base + 8192 + ao);
                }
#pragma unroll
                for (int np = 0; np < 2; np++) {
                    u32 bo = SWZ(rB + np * 16, kc + cB);
                    ldsm4(bh[np], base + 16384 + bo);
                    ldsm4(bl[np], base + 24576 + bo);
                }
#pragma unroll
                for (int mi = 0; mi < 2; mi++)
#pragma unroll
                    for (int ni = 0; ni < 4; ni++)
                        mmabf(c[mi][ni], ah[mi], &bh[ni >> 1][(ni & 1) * 2]);
#pragma unroll
                for (int mi = 0; mi < 2; mi++)
#pragma unroll
                    for (int ni = 0; ni < 4; ni++)
                        mmabf(c[mi][ni], ah[mi], &bl[ni >> 1][(ni & 1) * 2]);
#pragma unroll
                for (int mi = 0; mi < 2; mi++)
#pragma unroll
                    for (int ni = 0; ni < 4; ni++)
                        mmabf(c[mi][ni], al[mi], &bh[ni >> 1][(ni & 1) * 2]);
            }
            if (pre) {
                u32 h4[4] = {pack_h(v0.x, v0.y), pack_h(v0.z, v0.w), pack_h(v1.x, v1.y), pack_h(v1.z, v1.w)};
                u32 l4[4] = {pack_l(v0.x, v0.y), pack_l(v0.z, v0.w), pack_l(v1.x, v1.y), pack_l(v1.z, v1.w)};
                u32 o = PIPE + ((ch + 2) % 3) * 32768;
                *(uint4*)(smem + o + 16384 + SWZ(xrow, xq)) = *(uint4*)h4;
                *(uint4*)(smem + o + 24576 + SWZ(xrow, xq)) = *(uint4*)l4;
            }
        }
        // epilogue: write Ut smem (h/l, swizzled)
#pragma unroll
        for (int mi = 0; mi < 2; mi++)
#pragma unroll
            for (int ni = 0; ni < 4; ni++) {
                int m = mh * 128 + wx * 32 + ni * 8 + cp2;
                int j0 = wy * 32 + mi * 16 + g;
                float* d = c[mi][ni];
                u32 a0 = swzU(j0, m >> 3) + (m & 7) * 2;
                u32 a1 = swzU(j0 + 8, m >> 3) + (m & 7) * 2;
                *(u32*)(smem + a0) = pack_h(d[0], d[1]);
                *(u32*)(smem + 65536 + a0) = pack_l(d[0], d[1]);
                *(u32*)(smem + a1) = pack_h(d[2], d[3]);
                *(u32*)(smem + 65536 + a1) = pack_l(d[2], d[3]);
            }
        __syncthreads();
    }

    // ======== K2: B from smem Ut ========
    {
        const int xrow = tid >> 2, xq = tid & 3;
        float c[2][4][4];
#pragma unroll
        for (int i = 0; i < 2; i++)
#pragma unroll
            for (int j = 0; j < 4; j++)
#pragma unroll
                for (int r = 0; r < 4; r++) c[i][j][r] = 0.f;
        // A-ring: 3 stages x 16KB (Ah@0, Al@8192)
#pragma unroll
        for (int st = 0; st < 2; st++) {
            u32 b = sb + PIPE + st * 16384;
            cpa(b + SWZ(xrow, xq), &g_Tch[xrow * 256 + st * 32 + xq * 8]);
            cpa(b + 8192 + SWZ(xrow, xq), &g_Tcl[xrow * 256 + st * 32 + xq * 8]);
            CPC();
        }
        const int NCH = 8;
        for (int ch = 0; ch < NCH; ch++) {
            if (ch + 1 < NCH) { CPW1(); } else { CPW0(); }
            __syncthreads();
            if (ch + 2 < NCH) {
                u32 b = sb + PIPE + ((ch + 2) % 3) * 16384;
                cpa(b + SWZ(xrow, xq), &g_Tch[xrow * 256 + (ch + 2) * 32 + xq * 8]);
                cpa(b + 8192 + SWZ(xrow, xq), &g_Tcl[xrow * 256 + (ch + 2) * 32 + xq * 8]);
                CPC();
            }
            u32 base = sb + PIPE + (ch % 3) * 16384;
#pragma unroll
            for (int kk = 0; kk < 2; kk++) {
                u32 ah[2][4], al[2][4], bh[2][4], bl[2][4];
#pragma unroll
                for (int mi = 0; mi < 2; mi++) {
                    u32 ao = SWZ(rA + mi * 16, kk * 2 + cA);
                    ldsm4(ah[mi], base + ao);
                    ldsm4(al[mi], base + 8192 + ao);
                }
#pragma unroll
                for (int np = 0; np < 2; np++) {
                    int c16 = ch * 4 + kk * 2 + cB;
                    u32 bo = swzU(rB + np * 16, c16);
                    ldsm4(bh[np], sb + bo);
                    ldsm4(bl[np], sb + 65536 + bo);
                }
#pragma unroll
                for (int mi = 0; mi < 2; mi++)
#pragma unroll
                    for (int ni = 0; ni < 4; ni++)
                        mmabf(c[mi][ni], ah[mi], &bh[ni >> 1][(ni & 1) * 2]);
#pragma unroll
                for (int mi = 0; mi < 2; mi++)
#pragma unroll
                    for (int ni = 0; ni < 4; ni++)
                        mmabf(c[mi][ni], ah[mi], &bl[ni >> 1][(ni & 1) * 2]);
#pragma unroll
                for (int mi = 0; mi < 2; mi++)
#pragma unroll
                    for (int ni = 0; ni < 4; ni++)
                        mmabf(c[mi][ni], al[mi], &bh[ni >> 1][(ni & 1) * 2]);
            }
        }
        __syncthreads();
        // stage R into smem fp32 F[128][132] at PIPE, then combine -> CS
        float* F = (float*)(smem + PIPE);
#pragma unroll
        for (int mi = 0; mi < 2; mi++)
#pragma unroll
            for (int ni = 0; ni < 4; ni++) {
                int col = wx * 32 + ni * 8 + cp2;
                int r0 = wy * 32 + mi * 16 + g;
                float* d = c[mi][ni];
                F[r0 * 132 + col] = d[0];
                F[r0 * 132 + col + 1] = d[1];
                F[(r0 + 8) * 132 + col] = d[2];
                F[(r0 + 8) * 132 + col + 1] = d[3];
            }
        __syncthreads();
        const int b = img >> 6, ic = img & 63;
#pragma unroll
        for (int t = 0; t < 8; t++) {
            int p = tid + t * 512;
            int s1 = p >> 6, s2 = p & 63;
            float r00 = F[s1 * 132 + s2];
            float r01 = F[s1 * 132 + 64 + s2];
            float r10 = F[(64 + s1) * 132 + s2];
            float r11 = F[(64 + s1) * 132 + 64 + s2];
            int a = p * 1024 + ic * 16 + b;
            g_CS[a] = r00 - r11;
            g_CS[4194304 + a] = r10 + r01;
        }
    }
}

// ---------------- K3: channel mixing (fp32) ----------------
__device__ __forceinline__ ull pk2(float lo, float hi) {
    ull r; asm("mov.b64 %0, {%1, %2};" : "=l"(r) : "f"(lo), "f"(hi)); return r;
}
__device__ __forceinline__ float2 up2(ull v) {
    float2 f; asm("mov.b64 {%0, %1}, %2;" : "=f"(f.x), "=f"(f.y) : "l"(v)); return f;
}
__device__ __forceinline__ void fm2(ull& d, ull a, ull b) {
    asm("fma.rn.f32x2 %0, %1, %2, %0;" : "+l"(d) : "l"(a), "l"(b));
}
__global__ __launch_bounds__(256) void k_mix() {
    __shared__ float sC[1024], sS[1024];
    __shared__ float sW[4096], sWr[4096];
    const int mode = blockIdx.x;
    const int s1 = mode >> 6, s2 = mode & 63;
    const int f1 = (64 - s1) & 63, f2 = (64 - s2) & 63;
    const int tid = threadIdx.x;
    for (int t = tid; t < 1024; t += 256) {
        sC[t] = g_CS[mode * 1024 + t];
        sS[t] = g_CS[4194304 + mode * 1024 + t];
    }
    for (int t = tid; t < 4096; t += 256) {
        sW[t] = g_Wt[mode * 4096 + t];
        sWr[t] = g_Wt[(f1 * 64 + f2) * 4096 + t];
    }
    __syncthreads();
    const int o = tid & 63, bq = tid >> 6;
    ull acc01 = 0ull, acc23 = 0ull;
#pragma unroll 8
    for (int i = 0; i < 64; i++) {
        float wv = sW[i * 64 + o];
        float wr = sWr[i * 64 + o];
        ull ww = pk2(wv, wv), wwr = pk2(wr, wr);
        fm2(acc01, *(const ull*)&sC[i * 16 + bq * 4], ww);
        fm2(acc01, *(const ull*)&sS[i * 16 + bq * 4], wwr);
        fm2(acc23, *(const ull*)&sC[i * 16 + bq * 4 + 2], ww);
        fm2(acc23, *(const ull*)&sS[i * 16 + bq * 4 + 2], wwr);
    }
    float2 v01 = up2(acc01), v23 = up2(acc23);
    float vals[4] = {v01.x, v01.y, v23.x, v23.y};
#pragma unroll
    for (int r = 0; r < 4; r++) {
        int img2 = (bq * 4 + r) * 64 + o;
        bf16 h, l;
        bsplit(vals[r], h, l);
        g_Tth[img2 * 4096 + s2 * 64 + s1] = h;
        g_Ttl[img2 * 4096 + s2 * 64 + s1] = l;
    }
}

// ---------------- K45: fused inverse (per image) ----------------
// smem: Wm_h @0 (64K), Wm_l @65536 (64K), pipeline @131072 (64K), Tt @196608 (16K)
__global__ __launch_bounds__(512, 1) void k45(const float* __restrict__ bias,
                                              float* __restrict__ out) {
    extern __shared__ char smem[];
    u32 sb = smem_u32(smem);
    const int PIPE = 131072, TT = 196608;
    int tid = threadIdx.x, lane = tid & 31, w = tid >> 5;
    int wy = w >> 1, wx = w & 1;        // 8x2 warp grid
    int img = blockIdx.x;
    int g = lane >> 2, cp2 = (lane & 3) * 2;

    // Tt -> smem (h @TT, l @TT+8192), 128B-row swizzle
    {
        int r = tid >> 3, cc = tid & 7;
        cpa(sb + TT + swzT(r, cc), &g_Tth[img * 4096 + r * 64 + cc * 8]);
        cpa(sb + TT + 8192 + swzT(r, cc), &g_Ttl[img * 4096 + r * 64 + cc * 8]);
        CPC();
    }
    // A-ring: 2 stages x 32KB (Ah@0, Al@16384)
    auto issueA = [&](int slot) {
        int cc = slot >> 1, k0 = (slot & 1) * 32;
        const bf16* Ah = g_A5h + cc * 16384;
        const bf16* Al = g_A5l + cc * 16384;
        u32 b = sb + PIPE + (slot & 1) * 32768;
#pragma unroll
        for (int t = 0; t < 2; t++) {
            int f = tid + t * 512, row = f >> 2, q = f & 3;
            cpa(b + SWZ(row, q), &Ah[row * 64 + k0 + q * 8]);
            cpa(b + 16384 + SWZ(row, q), &Al[row * 64 + k0 + q * 8]);
        }
        CPC();
    };
    issueA(0); issueA(1);

    // ======== K4: two c-passes ========
    int rA = wy * 32 + (lane & 15), cA = lane >> 4;
    int rB = wx * 32 + (lane & 7) + ((lane >> 4) << 3), cB = (lane >> 3) & 1;
    for (int cpass = 0; cpass < 2; cpass++) {
        float acc[2][4][4];
#pragma unroll
        for (int i = 0; i < 2; i++)
#pragma unroll
            for (int j = 0; j < 4; j++)
#pragma unroll
                for (int r = 0; r < 4; r++) acc[i][j][r] = 0.f;
        for (int k = 0; k < 2; k++) {
            int slot = cpass * 2 + k;
            if (slot < 3) { CPW1(); } else { CPW0(); }
            __syncthreads();
            u32 stg = sb + PIPE + (slot & 1) * 32768;
#pragma unroll
            for (int kk = 0; kk < 2; kk++) {
                u32 ah[2][4], al[2][4], bh[2][4], bl[2][4];
#pragma unroll
                for (int mi = 0; mi < 2; mi++) {
                    u32 ao = SWZ(rA + mi * 16, kk * 2 + cA);
                    ldsm4(ah[mi], stg + ao);
                    ldsm4(al[mi], stg + 16384 + ao);
                }
#pragma unroll
                for (int np = 0; np < 2; np++) {
                    int c16 = k * 4 + kk * 2 + cB;
                    u32 bo = swzT(rB + np * 16, c16);
                    ldsm4(bh[np], sb + TT + bo);
                    ldsm4(bl[np], sb + TT + 8192 + bo);
                }
#pragma unroll
                for (int mi = 0; mi < 2; mi++)
#pragma unroll
                    for (int ni = 0; ni < 4; ni++)
                        mmabf(acc[mi][ni], ah[mi], &bh[ni >> 1][(ni & 1) * 2]);
#pragma unroll
                for (int mi = 0; mi < 2; mi++)
#pragma unroll
                    for (int ni = 0; ni < 4; ni++)
                        mmabf(acc[mi][ni], ah[mi], &bl[ni >> 1][(ni & 1) * 2]);
#pragma unroll
                for (int mi = 0; mi < 2; mi++)
#pragma unroll
                    for (int ni = 0; ni < 4; ni++)
                        mmabf(acc[mi][ni], al[mi], &bh[ni >> 1][(ni & 1) * 2]);
            }
            __syncthreads();
            if (slot + 2 < 4) issueA(slot + 2);
        }
        // epilogue: write Wmat smem
#pragma unroll
        for (int mi = 0; mi < 2; mi++)
#pragma unroll
            for (int ni = 0; ni < 4; ni++) {
                int col = cpass * 64 + wx * 32 + ni * 8 + cp2;
                int m0 = wy * 32 + mi * 16 + g;
                float* d = acc[mi][ni];
                u32 a0 = swzW(m0, col >> 3) + (col & 7) * 2;
                u32 a1 = swzW(m0 + 8, col >> 3) + (col & 7) * 2;
                *(u32*)(smem + a0) = pack_h(d[0], d[1]);
                *(u32*)(smem + 65536 + a0) = pack_l(d[0], d[1]);
                *(u32*)(smem + a1) = pack_h(d[2], d[3]);
                *(u32*)(smem + 65536 + a1) = pack_l(d[2], d[3]);
            }
    }
    __syncthreads();

    // ======== K5: A from smem Wmat, B = T5 ring ========
    const float bv = bias[img & 63];
    const float sc = 1.0f / 65536.0f;
    int rB5 = wx * 64 + (lane & 7) + ((lane >> 4) << 3);
    for (int nh = 0; nh < 2; nh++) {
        float c5[2][8][4];
#pragma unroll
        for (int i = 0; i < 2; i++)
#pragma unroll
            for (int j = 0; j < 8; j++)
#pragma unroll
                for (int r = 0; r < 4; r++) c5[i][j][r] = 0.f;
        // B-ring: 3 stages x 16KB (Bh@0, Bl@8192)
        int xrow = tid >> 2, xq = tid & 3;
#pragma unroll
        for (int st = 0; st < 2; st++) {
            u32 b = sb + PIPE + st * 16384;
            cpa(b + SWZ(xrow, xq), &g_T5h[(nh * 128 + xrow) * 128 + st * 32 + xq * 8]);
            cpa(b + 8192 + SWZ(xrow, xq), &g_T5l[(nh * 128 + xrow) * 128 + st * 32 + xq * 8]);
            CPC();
        }
        for (int ch = 0; ch < 4; ch++) {
            if (ch < 3) { CPW1(); } else { CPW0(); }
            __syncthreads();
            if (ch + 2 < 4) {
                u32 b = sb + PIPE + ((ch + 2) % 3) * 16384;
                cpa(b + SWZ(xrow, xq), &g_T5h[(nh * 128 + xrow) * 128 + (ch + 2) * 32 + xq * 8]);
                cpa(b + 8192 + SWZ(xrow, xq), &g_T5l[(nh * 128 + xrow) * 128 + (ch + 2) * 32 + xq * 8]);
                CPC();
            }
            u32 stg = sb + PIPE + (ch % 3) * 16384;
#pragma unroll
            for (int kk = 0; kk < 2; kk++) {
                u32 ah[2][4], al[2][4], bh[4][4], bl[4][4];
#pragma unroll
                for (int mi = 0; mi < 2; mi++) {
                    int c16 = ch * 4 + kk * 2 + cA;
                    u32 ao = swzW(rA + mi * 16, c16);
                    ldsm4(ah[mi], sb + ao);
                    ldsm4(al[mi], sb + 65536 + ao);
                }
#pragma unroll
                for (int np = 0; np < 4; np++) {
                    u32 bo = SWZ(rB5 + np * 16, kk * 2 + cB);
                    ldsm4(bh[np], stg + bo);
                    ldsm4(bl[np], stg + 8192 + bo);
                }
#pragma unroll
                for (int mi = 0; mi < 2; mi++)
#pragma unroll
                    for (int ni = 0; ni < 8; ni++)
                        mmabf(c5[mi][ni], ah[mi], &bh[ni >> 1][(ni & 1) * 2]);
#pragma unroll
                for (int mi = 0; mi < 2; mi++)
#pragma unroll
                    for (int ni = 0; ni < 8; ni++)
                        mmabf(c5[mi][ni], ah[mi], &bl[ni >> 1][(ni & 1) * 2]);
#pragma unroll
                for (int mi = 0; mi < 2; mi++)
#pragma unroll
                    for (int ni = 0; ni < 8; ni++)
                        mmabf(c5[mi][ni], al[mi], &bh[ni >> 1][(ni & 1) * 2]);
            }
        }
        // epilogue: bias + relu + store
#pragma unroll
        for (int mi = 0; mi < 2; mi++)
#pragma unroll
            for (int ni = 0; ni < 8; ni++) {
                int col = nh * 128 + wx * 64 + ni * 8 + cp2;
                float* d = c5[mi][ni];
#pragma unroll
                for (int half = 0; half < 2; half++) {
                    int m = wy * 32 + mi * 16 + g + half * 8;
                    float2 v;
                    v.x = fmaxf(fmaf(d[half * 2], sc, bv), 0.f);
                    v.y = fmaxf(fmaf(d[half * 2 + 1], sc, bv), 0.f);
                    *(float2*)&out[(size_t)img * 65536 + m * 256 + col] = v;
                }
            }
        __syncthreads();
    }
}

extern "C" void kernel_launch(void* const* d_in, const int* in_sizes, int n_in,
                              void* d_out, int out_size) {
    const float* x = (const float*)d_in[0];
    const float* wgt = (const float*)d_in[1];
    const float* bias = (const float*)d_in[2];
    float* out = (float*)d_out;

    cudaFuncSetAttribute(k12, cudaFuncAttributeMaxDynamicSharedMemorySize, 229376);
    cudaFuncSetAttribute(k45, cudaFuncAttributeMaxDynamicSharedMemorySize, 212992);

    k_tables<<<256, 128>>>();
    k_wt<<<dim3(128, 128), dim3(32, 8)>>>(wgt);
    k12<<<1024, 512, 229376>>>(x);
    k_mix<<<4096, 256>>>();
    k45<<<1024, 512, 212992>>>(bias, out);
}

// round 12
// speedup vs baseline: 1.3731x; 1.1824x over previous
#include <cuda_runtime.h>
#include <cuda_bf16.h>
#include <cstdint>

// HartleySpectralConv2d B=16,CI=CO=64,H=W=256, modes 64x64.
// Split-bf16 HMMA GEMMs. R12: k_mix on tensor cores (split-bf16 weights in
// MMA layout), packed Tot (h,l) u32; K1+K2 and K4+K5 remain smem-fused.

using bf16 = __nv_bfloat16;
using u32 = uint32_t; using ull = unsigned long long;

__device__ bf16 g_Tch[128 * 256], g_Tcl[128 * 256];       // [j][a] K-major
__device__ bf16 g_A5h[2 * 256 * 64], g_A5l[2 * 256 * 64]; // [(c*256+m)][s1]
__device__ bf16 g_T5h[256 * 128], g_T5l[256 * 128];       // [n][c*64+s2]
__device__ bf16 g_Wth[4096 * 4096], g_Wtl[4096 * 4096];   // [mode][o*64+i] split
__device__ float g_CS[2 * 4096 * 1024];                   // [comp][mode][ci*16+b]
__device__ u32 g_Ttp[1024 * 4096];                        // [img][s2*64+s1] packed(h,l)

// ---------------- helpers ----------------
__device__ __forceinline__ u32 smem_u32(const void* p) {
    u32 a;
    asm("{ .reg .u64 t; cvta.to.shared.u64 t, %1; cvt.u32.u64 %0, t; }" : "=r"(a) : "l"(p));
    return a;
}
__device__ __forceinline__ void ldsm4(u32* r, u32 a) {
    asm volatile("ldmatrix.sync.aligned.m8n8.x4.shared.b16 {%0,%1,%2,%3}, [%4];"
                 : "=r"(r[0]), "=r"(r[1]), "=r"(r[2]), "=r"(r[3]) : "r"(a));
}
__device__ __forceinline__ void ldsm2(u32* r, u32 a) {
    asm volatile("ldmatrix.sync.aligned.m8n8.x2.shared.b16 {%0,%1}, [%2];"
                 : "=r"(r[0]), "=r"(r[1]) : "r"(a));
}
__device__ __forceinline__ void mmabf(float* d, const u32* a, const u32* b) {
    asm volatile("mma.sync.aligned.m16n8k16.row.col.f32.bf16.bf16.f32 "
                 "{%0,%1,%2,%3}, {%4,%5,%6,%7}, {%8,%9}, {%0,%1,%2,%3};"
                 : "+f"(d[0]), "+f"(d[1]), "+f"(d[2]), "+f"(d[3])
                 : "r"(a[0]), "r"(a[1]), "r"(a[2]), "r"(a[3]), "r"(b[0]), "r"(b[1]));
}
__device__ __forceinline__ void cpa(u32 s, const void* g) {
    asm volatile("cp.async.cg.shared.global [%0], [%1], 16;" :: "r"(s), "l"(g));
}
#define CPC()  asm volatile("cp.async.commit_group;" ::: "memory")
#define CPW1() asm volatile("cp.async.wait_group 1;" ::: "memory")
#define CPW0() asm volatile("cp.async.wait_group 0;" ::: "memory")

__device__ __forceinline__ u32 pack_bf(bf16 a, bf16 b) {
    return (u32)__bfloat16_as_ushort(a) | ((u32)__bfloat16_as_ushort(b) << 16);
}
__device__ __forceinline__ void bsplit(float v, bf16& h, bf16& l) {
    h = __float2bfloat16(v);
    l = __float2bfloat16(v - __bfloat162float(h));
}
__device__ __forceinline__ u32 pack_h(float a, float b) {
    bf16 h0, l0, h1, l1; bsplit(a, h0, l0); bsplit(b, h1, l1); return pack_bf(h0, h1);
}
__device__ __forceinline__ u32 pack_l(float a, float b) {
    bf16 h0, l0, h1, l1; bsplit(a, h0, l0); bsplit(b, h1, l1); return pack_bf(l0, l1);
}

// swizzles (conflict-free for 8-row ldsm phases)
__device__ __forceinline__ u32 SWZ(int row, int c) {           // 64B rows
    return (u32)(row * 64 + ((c ^ ((row >> 1) & 3)) << 4));
}
__device__ __forceinline__ u32 swzU(int j, int c16) {          // 512B rows
    return (u32)(j * 512 + ((((c16 ^ j) & 7) | (c16 & 24)) << 4));
}
__device__ __forceinline__ u32 swzW(int m, int c16) {          // 256B rows
    return (u32)(m * 256 + ((((c16 ^ m) & 7) | (c16 & 8)) << 4));
}
__device__ __forceinline__ u32 swzT(int r, int c16) {          // 128B rows
    return (u32)(r * 128 + ((c16 ^ (r & 7)) << 4));
}

// ---------------- K0: split trig tables ----------------
__global__ void k_tables() {
    int a = blockIdx.x, b = threadIdx.x;
    int s = b & 63, k = s - 32;
    int q = ((k * a) % 256 + 256) % 256;
    float sv, cv;
    sincospif((float)q * (1.0f / 128.0f), &sv, &cv);
    float tc = (b < 64) ? cv : sv;
    bf16 h, l;
    bsplit(tc, h, l);
    g_Tch[b * 256 + a] = h; g_Tcl[b * 256 + a] = l;
    g_T5h[a * 128 + b] = h; g_T5l[a * 128 + b] = l;
    int c = b >> 6;
    float a5 = c ? (cv - sv) : (cv + sv);
    bsplit(a5, h, l);
    g_A5h[(c * 256 + a) * 64 + s] = h;
    g_A5l[(c * 256 + a) * 64 + s] = l;
}

// ---------------- Kw: weight transpose + split: w[i,o,xy] -> Wt[xy][o*64+i] ----------------
__global__ __launch_bounds__(256) void k_wt(const float* __restrict__ w) {
    __shared__ float tile[64][65];
    int bx = blockIdx.x;   // xy chunk (64 wide)
    int o = blockIdx.y;    // output channel
    int tid = threadIdx.x;
    int tx = tid & 63, tg = tid >> 6;
#pragma unroll
    for (int it = 0; it < 16; it++) {
        int i = tg + it * 4;
        tile[i][tx] = w[(size_t)(i * 64 + o) * 4096 + bx * 64 + tx];
    }
    __syncthreads();
#pragma unroll
    for (int it = 0; it < 16; it++) {
        int xy = tg + it * 4;
        float v = tile[tx][xy];
        bf16 h, l;
        bsplit(v, h, l);
        size_t dst = (size_t)(bx * 64 + xy) * 4096 + o * 64 + tx;
        g_Wth[dst] = h;
        g_Wtl[dst] = l;
    }
}

// ---------------- K12: fused forward (per image) ----------------
// smem: Ut_h @0 (64K), Ut_l @65536 (64K), pipeline @131072 (96K)
__global__ __launch_bounds__(512, 1) void k12(const float* __restrict__ x) {
    extern __shared__ char smem[];
    u32 sb = smem_u32(smem);
    const int PIPE = 131072;
    int tid = threadIdx.x, lane = tid & 31, w = tid >> 5;
    int wy = w >> 2, wx = w & 3;        // 4x4 warp grid
    int img = blockIdx.x;
    int g = lane >> 2, cp2 = (lane & 3) * 2;
    int rA = wy * 32 + (lane & 15), cA = lane >> 4;
    int rB = wx * 32 + (lane & 7) + ((lane >> 4) << 3), cB = (lane >> 3) & 1;

    // ======== K1: two passes over m-halves ========
    for (int mh = 0; mh < 2; mh++) {
        const float* xb = x + (size_t)img * 65536 + mh * 128 * 256;
        const int xrow = tid >> 2, xq = tid & 3;
        float c[2][4][4];
#pragma unroll
        for (int i = 0; i < 2; i++)
#pragma unroll
            for (int j = 0; j < 4; j++)
#pragma unroll
                for (int r = 0; r < 4; r++) c[i][j][r] = 0.f;
#pragma unroll
        for (int st = 0; st < 2; st++) {
            u32 b = sb + PIPE + st * 32768;
            cpa(b + SWZ(xrow, xq), &g_Tch[xrow * 256 + st * 32 + xq * 8]);
            cpa(b + 8192 + SWZ(xrow, xq), &g_Tcl[xrow * 256 + st * 32 + xq * 8]);
            CPC();
            const float* s = &xb[xrow * 256 + st * 32 + xq * 8];
            float4 v0 = *(const float4*)s, v1 = *(const float4*)(s + 4);
            u32 h4[4] = {pack_h(v0.x, v0.y), pack_h(v0.z, v0.w), pack_h(v1.x, v1.y), pack_h(v1.z, v1.w)};
            u32 l4[4] = {pack_l(v0.x, v0.y), pack_l(v0.z, v0.w), pack_l(v1.x, v1.y), pack_l(v1.z, v1.w)};
            *(uint4*)(smem + PIPE + st * 32768 + 16384 + SWZ(xrow, xq)) = *(uint4*)h4;
            *(uint4*)(smem + PIPE + st * 32768 + 24576 + SWZ(xrow, xq)) = *(uint4*)l4;
        }
        const int NCH = 8;
        for (int ch = 0; ch < NCH; ch++) {
            if (ch + 1 < NCH) { CPW1(); } else { CPW0(); }
            __syncthreads();
            bool pre = (ch + 2 < NCH);
            float4 v0, v1;
            if (pre) {
                const float* s = &xb[xrow * 256 + (ch + 2) * 32 + xq * 8];
                v0 = *(const float4*)s; v1 = *(const float4*)(s + 4);
                u32 b = sb + PIPE + ((ch + 2) % 3) * 32768;
                cpa(b + SWZ(xrow, xq), &g_Tch[xrow * 256 + (ch + 2) * 32 + xq * 8]);
                cpa(b + 8192 + SWZ(xrow, xq), &g_Tcl[xrow * 256 + (ch + 2) * 32 + xq * 8]);
                CPC();
            }
            u32 base = sb + PIPE + (ch % 3) * 32768;
#pragma unroll
            for (int kk = 0; kk < 2; kk++) {
                int kc = kk * 2;
                u32 ah[2][4], al[2][4], bh[2][4], bl[2][4];
#pragma unroll
                for (int mi = 0; mi < 2; mi++) {
                    u32 ao = SWZ(rA + mi * 16, kc + cA);
                    ldsm4(ah[mi], base + ao);
                    ldsm4(al[mi], base + 8192 + ao);
                }
#pragma unroll
                for (int np = 0; np < 2; np++) {
                    u32 bo = SWZ(rB + np * 16, kc + cB);
                    ldsm4(bh[np], base + 16384 + bo);
                    ldsm4(bl[np], base + 24576 + bo);
                }
#pragma unroll
                for (int mi = 0; mi < 2; mi++)
#pragma unroll
                    for (int ni = 0; ni < 4; ni++)
                        mmabf(c[mi][ni], ah[mi], &bh[ni >> 1][(ni & 1) * 2]);
#pragma unroll
                for (int mi = 0; mi < 2; mi++)
#pragma unroll
                    for (int ni = 0; ni < 4; ni++)
                        mmabf(c[mi][ni], ah[mi], &bl[ni >> 1][(ni & 1) * 2]);
#pragma unroll
                for (int mi = 0; mi < 2; mi++)
#pragma unroll
                    for (int ni = 0; ni < 4; ni++)
                        mmabf(c[mi][ni], al[mi], &bh[ni >> 1][(ni & 1) * 2]);
            }
            if (pre) {
                u32 h4[4] = {pack_h(v0.x, v0.y), pack_h(v0.z, v0.w), pack_h(v1.x, v1.y), pack_h(v1.z, v1.w)};
                u32 l4[4] = {pack_l(v0.x, v0.y), pack_l(v0.z, v0.w), pack_l(v1.x, v1.y), pack_l(v1.z, v1.w)};
                u32 o = PIPE + ((ch + 2) % 3) * 32768;
                *(uint4*)(smem + o + 16384 + SWZ(xrow, xq)) = *(uint4*)h4;
                *(uint4*)(smem + o + 24576 + SWZ(xrow, xq)) = *(uint4*)l4;
            }
        }
#pragma unroll
        for (int mi = 0; mi < 2; mi++)
#pragma unroll
            for (int ni = 0; ni < 4; ni++) {
                int m = mh * 128 + wx * 32 + ni * 8 + cp2;
                int j0 = wy * 32 + mi * 16 + g;
                float* d = c[mi][ni];
                u32 a0 = swzU(j0, m >> 3) + (m & 7) * 2;
                u32 a1 = swzU(j0 + 8, m >> 3) + (m & 7) * 2;
                *(u32*)(smem + a0) = pack_h(d[0], d[1]);
                *(u32*)(smem + 65536 + a0) = pack_l(d[0], d[1]);
                *(u32*)(smem + a1) = pack_h(d[2], d[3]);
                *(u32*)(smem + 65536 + a1) = pack_l(d[2], d[3]);
            }
        __syncthreads();
    }

    // ======== K2: B from smem Ut ========
    {
        const int xrow = tid >> 2, xq = tid & 3;
        float c[2][4][4];
#pragma unroll
        for (int i = 0; i < 2; i++)
#pragma unroll
            for (int j = 0; j < 4; j++)
#pragma unroll
                for (int r = 0; r < 4; r++) c[i][j][r] = 0.f;
#pragma unroll
        for (int st = 0; st < 2; st++) {
            u32 b = sb + PIPE + st * 16384;
            cpa(b + SWZ(xrow, xq), &g_Tch[xrow * 256 + st * 32 + xq * 8]);
            cpa(b + 8192 + SWZ(xrow, xq), &g_Tcl[xrow * 256 + st * 32 + xq * 8]);
            CPC();
        }
        const int NCH = 8;
        for (int ch = 0; ch < NCH; ch++) {
            if (ch + 1 < NCH) { CPW1(); } else { CPW0(); }
            __syncthreads();
            if (ch + 2 < NCH) {
                u32 b = sb + PIPE + ((ch + 2) % 3) * 16384;
                cpa(b + SWZ(xrow, xq), &g_Tch[xrow * 256 + (ch + 2) * 32 + xq * 8]);
                cpa(b + 8192 + SWZ(xrow, xq), &g_Tcl[xrow * 256 + (ch + 2) * 32 + xq * 8]);
                CPC();
            }
            u32 base = sb + PIPE + (ch % 3) * 16384;
#pragma unroll
            for (int kk = 0; kk < 2; kk++) {
                u32 ah[2][4], al[2][4], bh[2][4], bl[2][4];
#pragma unroll
                for (int mi = 0; mi < 2; mi++) {
                    u32 ao = SWZ(rA + mi * 16, kk * 2 + cA);
                    ldsm4(ah[mi], base + ao);
                    ldsm4(al[mi], base + 8192 + ao);
                }
#pragma unroll
                for (int np = 0; np < 2; np++) {
                    int c16 = ch * 4 + kk * 2 + cB;
                    u32 bo = swzU(rB + np * 16, c16);
                    ldsm4(bh[np], sb + bo);
                    ldsm4(bl[np], sb + 65536 + bo);
                }
#pragma unroll
                for (int mi = 0; mi < 2; mi++)
#pragma unroll
                    for (int ni = 0; ni < 4; ni++)
                        mmabf(c[mi][ni], ah[mi], &bh[ni >> 1][(ni & 1) * 2]);
#pragma unroll
                for (int mi = 0; mi < 2; mi++)
#pragma unroll
                    for (int ni = 0; ni < 4; ni++)
                        mmabf(c[mi][ni], ah[mi], &bl[ni >> 1][(ni & 1) * 2]);
#pragma unroll
                for (int mi = 0; mi < 2; mi++)
#pragma unroll
                    for (int ni = 0; ni < 4; ni++)
                        mmabf(c[mi][ni], al[mi], &bh[ni >> 1][(ni & 1) * 2]);
            }
        }
        __syncthreads();
        float* F = (float*)(smem + PIPE);
#pragma unroll
        for (int mi = 0; mi < 2; mi++)
#pragma unroll
            for (int ni = 0; ni < 4; ni++) {
                int col = wx * 32 + ni * 8 + cp2;
                int r0 = wy * 32 + mi * 16 + g;
                float* d = c[mi][ni];
                F[r0 * 132 + col] = d[0];
                F[r0 * 132 + col + 1] = d[1];
                F[(r0 + 8) * 132 + col] = d[2];
                F[(r0 + 8) * 132 + col + 1] = d[3];
            }
        __syncthreads();
        const int b = img >> 6, ic = img & 63;
#pragma unroll
        for (int t = 0; t < 8; t++) {
            int p = tid + t * 512;
            int s1 = p >> 6, s2 = p & 63;
            float r00 = F[s1 * 132 + s2];
            float r01 = F[s1 * 132 + 64 + s2];
            float r10 = F[(64 + s1) * 132 + s2];
            float r11 = F[(64 + s1) * 132 + 64 + s2];
            int a = p * 1024 + ic * 16 + b;
            g_CS[a] = r00 - r11;
            g_CS[4194304 + a] = r10 + r01;
        }
    }
}

// ---------------- K3: channel mixing (split-bf16 HMMA) ----------------
// smem: Ch@0 Cl@2048 Sh@4096 Sl@6144 (2KB ea), Wh@8192 Wl@16384 Wrh@24576 Wrl@32768 (8KB ea)
__global__ __launch_bounds__(256) void k_mix() {
    __shared__ __align__(16) char sm[40960];
    u32 sb = smem_u32(sm);
    const int mode = blockIdx.x;
    const int s1 = mode >> 6, s2 = mode & 63;
    const int fmode = (((64 - s1) & 63) << 6) | ((64 - s2) & 63);
    const int tid = threadIdx.x, lane = tid & 31, w = tid >> 5;

    // W tiles via cp.async (bf16, [o][i] layout, swzT)
#pragma unroll
    for (int t = 0; t < 2; t++) {
        int f = tid + t * 256;
        int o = f >> 3, c16 = f & 7;
        size_t src = (size_t)mode * 4096 + o * 64 + c16 * 8;
        size_t srcf = (size_t)fmode * 4096 + o * 64 + c16 * 8;
        cpa(sb + 8192 + swzT(o, c16), &g_Wth[src]);
        cpa(sb + 16384 + swzT(o, c16), &g_Wtl[src]);
        cpa(sb + 24576 + swzT(o, c16), &g_Wth[srcf]);
        cpa(sb + 32768 + swzT(o, c16), &g_Wtl[srcf]);
    }
    CPC();
    // CS fp32 -> split bf16 A tiles [b(16)][i(64)]
    {
        float4 cv = *(const float4*)&g_CS[mode * 1024 + tid * 4];
        float4 sv = *(const float4*)&g_CS[4194304 + mode * 1024 + tid * 4];
        float cva[4] = {cv.x, cv.y, cv.z, cv.w}, sva[4] = {sv.x, sv.y, sv.z, sv.w};
#pragma unroll
        for (int q = 0; q < 4; q++) {
            int j = tid * 4 + q;
            int b = j & 15, ci = j >> 4;
            u32 a = swzT(b, ci >> 3) + (ci & 7) * 2;
            bf16 h, l;
            bsplit(cva[q], h, l);
            *(unsigned short*)(sm + a) = __bfloat16_as_ushort(h);
            *(unsigned short*)(sm + 2048 + a) = __bfloat16_as_ushort(l);
            bsplit(sva[q], h, l);
            *(unsigned short*)(sm + 4096 + a) = __bfloat16_as_ushort(h);
            *(unsigned short*)(sm + 6144 + a) = __bfloat16_as_ushort(l);
        }
    }
    CPW0();
    __syncthreads();
    // warp w -> n8 slice of o
    float acc[4] = {0.f, 0.f, 0.f, 0.f};
    const int o0 = w * 8;
    const int arow = lane & 15, ac = lane >> 4;
    const int brow = o0 + (lane & 7), bc = (lane >> 3) & 1;
#pragma unroll
    for (int kc = 0; kc < 4; kc++) {
        u32 ach[4], acl[4], ash[4], asl[4];
        u32 ao = swzT(arow, kc * 2 + ac);
        ldsm4(ach, sb + ao);
        ldsm4(acl, sb + 2048 + ao);
        ldsm4(ash, sb + 4096 + ao);
        ldsm4(asl, sb + 6144 + ao);
        u32 bh[2], bl[2], brh[2], brl[2];
        u32 bo = swzT(brow, kc * 2 + bc);
        ldsm2(bh, sb + 8192 + bo);
        ldsm2(bl, sb + 16384 + bo);
        ldsm2(brh, sb + 24576 + bo);
        ldsm2(brl, sb + 32768 + bo);
        mmabf(acc, ach, bh);
        mmabf(acc, ach, bl);
        mmabf(acc, acl, bh);
        mmabf(acc, ash, brh);
        mmabf(acc, ash, brl);
        mmabf(acc, asl, brh);
    }
    // epilogue: Tot[b][o] -> packed (h,l) at [img2][s2*64+s1]
    const int g = lane >> 2, cp2 = (lane & 3) * 2;
    const int tpos = s2 * 64 + s1;
#pragma unroll
    for (int half = 0; half < 2; half++) {
        int b = g + half * 8;
        bf16 h, l;
        bsplit(acc[half * 2], h, l);
        g_Ttp[(size_t)(b * 64 + o0 + cp2) * 4096 + tpos] = pack_bf(h, l);
        bsplit(acc[half * 2 + 1], h, l);
        g_Ttp[(size_t)(b * 64 + o0 + cp2 + 1) * 4096 + tpos] = pack_bf(h, l);
    }
}

// ---------------- K45: fused inverse (per image) ----------------
// smem: Wm_h @0 (64K), Wm_l @65536 (64K), pipeline @131072 (64K), Tt @196608 (16K)
__global__ __launch_bounds__(512, 1) void k45(const float* __restrict__ bias,
                                              float* __restrict__ out) {
    extern __shared__ char smem[];
    u32 sb = smem_u32(smem);
    const int PIPE = 131072, TT = 196608;
    int tid = threadIdx.x, lane = tid & 31, w = tid >> 5;
    int wy = w >> 1, wx = w & 1;        // 8x2 warp grid
    int img = blockIdx.x;
    int g = lane >> 2, cp2 = (lane & 3) * 2;

    // A-ring: 2 stages x 32KB (Ah@0, Al@16384)
    auto issueA = [&](int slot) {
        int cc = slot >> 1, k0 = (slot & 1) * 32;
        const bf16* Ah = g_A5h + cc * 16384;
        const bf16* Al = g_A5l + cc * 16384;
        u32 b = sb + PIPE + (slot & 1) * 32768;
#pragma unroll
        for (int t = 0; t < 2; t++) {
            int f = tid + t * 512, row = f >> 2, q = f & 3;
            cpa(b + SWZ(row, q), &Ah[row * 64 + k0 + q * 8]);
            cpa(b + 16384 + SWZ(row, q), &Al[row * 64 + k0 + q * 8]);
        }
        CPC();
    };
    issueA(0); issueA(1);

    // unpack packed Tot into h/l swizzled tiles (TT, TT+8192)
#pragma unroll
    for (int t = 0; t < 8; t++) {
        int p = tid + t * 512;
        u32 v = g_Ttp[(size_t)img * 4096 + p];
        int r = p >> 6, cc = p & 63;
        u32 a = swzT(r, cc >> 3) + (cc & 7) * 2;
        *(unsigned short*)(smem + TT + a) = (unsigned short)(v & 0xFFFF);
        *(unsigned short*)(smem + TT + 8192 + a) = (unsigned short)(v >> 16);
    }

    // ======== K4: two c-passes ========
    int rA = wy * 32 + (lane & 15), cA = lane >> 4;
    int rB = wx * 32 + (lane & 7) + ((lane >> 4) << 3), cB = (lane >> 3) & 1;
    for (int cpass = 0; cpass < 2; cpass++) {
        float acc[2][4][4];
#pragma unroll
        for (int i = 0; i < 2; i++)
#pragma unroll
            for (int j = 0; j < 4; j++)
#pragma unroll
                for (int r = 0; r < 4; r++) acc[i][j][r] = 0.f;
        for (int k = 0; k < 2; k++) {
            int slot = cpass * 2 + k;
            if (slot < 3) { CPW1(); } else { CPW0(); }
            __syncthreads();
            u32 stg = sb + PIPE + (slot & 1) * 32768;
#pragma unroll
            for (int kk = 0; kk < 2; kk++) {
                u32 ah[2][4], al[2][4], bh[2][4], bl[2][4];
#pragma unroll
                for (int mi = 0; mi < 2; mi++) {
                    u32 ao = SWZ(rA + mi * 16, kk * 2 + cA);
                    ldsm4(ah[mi], stg + ao);
                    ldsm4(al[mi], stg + 16384 + ao);
                }
#pragma unroll
                for (int np = 0; np < 2; np++) {
                    int c16 = k * 4 + kk * 2 + cB;
                    u32 bo = swzT(rB + np * 16, c16);
                    ldsm4(bh[np], sb + TT + bo);
                    ldsm4(bl[np], sb + TT + 8192 + bo);
                }
#pragma unroll
                for (int mi = 0; mi < 2; mi++)
#pragma unroll
                    for (int ni = 0; ni < 4; ni++)
                        mmabf(acc[mi][ni], ah[mi], &bh[ni >> 1][(ni & 1) * 2]);
#pragma unroll
                for (int mi = 0; mi < 2; mi++)
#pragma unroll
                    for (int ni = 0; ni < 4; ni++)
                        mmabf(acc[mi][ni], ah[mi], &bl[ni >> 1][(ni & 1) * 2]);
#pragma unroll
                for (int mi = 0; mi < 2; mi++)
#pragma unroll
                    for (int ni = 0; ni < 4; ni++)
                        mmabf(acc[mi][ni], al[mi], &bh[ni >> 1][(ni & 1) * 2]);
            }
            __syncthreads();
            if (slot + 2 < 4) issueA(slot + 2);
        }
#pragma unroll
        for (int mi = 0; mi < 2; mi++)
#pragma unroll
            for (int ni = 0; ni < 4; ni++) {
                int col = cpass * 64 + wx * 32 + ni * 8 + cp2;
                int m0 = wy * 32 + mi * 16 + g;
                float* d = acc[mi][ni];
                u32 a0 = swzW(m0, col >> 3) + (col & 7) * 2;
                u32 a1 = swzW(m0 + 8, col >> 3) + (col & 7) * 2;
                *(u32*)(smem + a0) = pack_h(d[0], d[1]);
                *(u32*)(smem + 65536 + a0) = pack_l(d[0], d[1]);
                *(u32*)(smem + a1) = pack_h(d[2], d[3]);
                *(u32*)(smem + 65536 + a1) = pack_l(d[2], d[3]);
            }
    }
    __syncthreads();

    // ======== K5: A from smem Wmat, B = T5 ring ========
    const float bv = bias[img & 63];
    const float sc = 1.0f / 65536.0f;
    int rB5 = wx * 64 + (lane & 7) + ((lane >> 4) << 3);
    for (int nh = 0; nh < 2; nh++) {
        float c5[2][8][4];
#pragma unroll
        for (int i = 0; i < 2; i++)
#pragma unroll
            for (int j = 0; j < 8; j++)
#pragma unroll
                for (int r = 0; r < 4; r++) c5[i][j][r] = 0.f;
        int xrow = tid >> 2, xq = tid & 3;
#pragma unroll
        for (int st = 0; st < 2; st++) {
            u32 b = sb + PIPE + st * 16384;
            cpa(b + SWZ(xrow, xq), &g_T5h[(nh * 128 + xrow) * 128 + st * 32 + xq * 8]);
            cpa(b + 8192 + SWZ(xrow, xq), &g_T5l[(nh * 128 + xrow) * 128 + st * 32 + xq * 8]);
            CPC();
        }
        for (int ch = 0; ch < 4; ch++) {
            if (ch < 3) { CPW1(); } else { CPW0(); }
            __syncthreads();
            if (ch + 2 < 4) {
                u32 b = sb + PIPE + ((ch + 2) % 3) * 16384;
                cpa(b + SWZ(xrow, xq), &g_T5h[(nh * 128 + xrow) * 128 + (ch + 2) * 32 + xq * 8]);
                cpa(b + 8192 + SWZ(xrow, xq), &g_T5l[(nh * 128 + xrow) * 128 + (ch + 2) * 32 + xq * 8]);
                CPC();
            }
            u32 stg = sb + PIPE + (ch % 3) * 16384;
#pragma unroll
            for (int kk = 0; kk < 2; kk++) {
                u32 ah[2][4], al[2][4], bh[4][4], bl[4][4];
#pragma unroll
                for (int mi = 0; mi < 2; mi++) {
                    int c16 = ch * 4 + kk * 2 + cA;
                    u32 ao = swzW(rA + mi * 16, c16);
                    ldsm4(ah[mi], sb + ao);
                    ldsm4(al[mi], sb + 65536 + ao);
                }
#pragma unroll
                for (int np = 0; np < 4; np++) {
                    u32 bo = SWZ(rB5 + np * 16, kk * 2 + cB);
                    ldsm4(bh[np], stg + bo);
                    ldsm4(bl[np], stg + 8192 + bo);
                }
#pragma unroll
                for (int mi = 0; mi < 2; mi++)
#pragma unroll
                    for (int ni = 0; ni < 8; ni++)
                        mmabf(c5[mi][ni], ah[mi], &bh[ni >> 1][(ni & 1) * 2]);
#pragma unroll
                for (int mi = 0; mi < 2; mi++)
#pragma unroll
                    for (int ni = 0; ni < 8; ni++)
                        mmabf(c5[mi][ni], ah[mi], &bl[ni >> 1][(ni & 1) * 2]);
#pragma unroll
                for (int mi = 0; mi < 2; mi++)
#pragma unroll
                    for (int ni = 0; ni < 8; ni++)
                        mmabf(c5[mi][ni], al[mi], &bh[ni >> 1][(ni & 1) * 2]);
            }
        }
#pragma unroll
        for (int mi = 0; mi < 2; mi++)
#pragma unroll
            for (int ni = 0; ni < 8; ni++) {
                int col = nh * 128 + wx * 64 + ni * 8 + cp2;
                float* d = c5[mi][ni];
#pragma unroll
                for (int half = 0; half < 2; half++) {
                    int m = wy * 32 + mi * 16 + g + half * 8;
                    float2 v;
                    v.x = fmaxf(fmaf(d[half * 2], sc, bv), 0.f);
                    v.y = fmaxf(fmaf(d[half * 2 + 1], sc, bv), 0.f);
                    *(float2*)&out[(size_t)img * 65536 + m * 256 + col] = v;
                }
            }
        __syncthreads();
    }
}

extern "C" void kernel_launch(void* const* d_in, const int* in_sizes, int n_in,
                              void* d_out, int out_size) {
    const float* x = (const float*)d_in[0];
    const float* wgt = (const float*)d_in[1];
    const float* bias = (const float*)d_in[2];
    float* out = (float*)d_out;

    cudaFuncSetAttribute(k12, cudaFuncAttributeMaxDynamicSharedMemorySize, 229376);
    cudaFuncSetAttribute(k45, cudaFuncAttributeMaxDynamicSharedMemorySize, 212992);

    k_tables<<<256, 128>>>();
    k_wt<<<dim3(64, 64), 256>>>(wgt);
    k12<<<1024, 512, 229376>>>(x);
    k_mix<<<4096, 256>>>();
    k45<<<1024, 512, 212992>>>(bias, out);
}

// round 13
// speedup vs baseline: 1.3824x; 1.0067x over previous
#include <cuda_runtime.h>
#include <cuda_bf16.h>
#include <cstdint>

// HartleySpectralConv2d B=16,CI=CO=64,H=W=256, modes 64x64.
// Split-bf16 HMMA. R13: k_mix processes (mode,flip) pairs (halves W traffic);
// k_wt forked onto side stream overlapping k12.

using bf16 = __nv_bfloat16;
using u32 = uint32_t; using ull = unsigned long long;

__device__ bf16 g_Tch[128 * 256], g_Tcl[128 * 256];       // [j][a] K-major
__device__ bf16 g_A5h[2 * 256 * 64], g_A5l[2 * 256 * 64]; // [(c*256+m)][s1]
__device__ bf16 g_T5h[256 * 128], g_T5l[256 * 128];       // [n][c*64+s2]
__device__ bf16 g_Wth[4096 * 4096], g_Wtl[4096 * 4096];   // [mode][o*64+i] split
__device__ float g_CS[2 * 4096 * 1024];                   // [comp][mode][ci*16+b]
__device__ u32 g_Ttp[1024 * 4096];                        // [img][s2*64+s1] packed(h,l)

// ---------------- helpers ----------------
__device__ __forceinline__ u32 smem_u32(const void* p) {
    u32 a;
    asm("{ .reg .u64 t; cvta.to.shared.u64 t, %1; cvt.u32.u64 %0, t; }" : "=r"(a) : "l"(p));
    return a;
}
__device__ __forceinline__ void ldsm4(u32* r, u32 a) {
    asm volatile("ldmatrix.sync.aligned.m8n8.x4.shared.b16 {%0,%1,%2,%3}, [%4];"
                 : "=r"(r[0]), "=r"(r[1]), "=r"(r[2]), "=r"(r[3]) : "r"(a));
}
__device__ __forceinline__ void ldsm2(u32* r, u32 a) {
    asm volatile("ldmatrix.sync.aligned.m8n8.x2.shared.b16 {%0,%1}, [%2];"
                 : "=r"(r[0]), "=r"(r[1]) : "r"(a));
}
__device__ __forceinline__ void mmabf(float* d, const u32* a, const u32* b) {
    asm volatile("mma.sync.aligned.m16n8k16.row.col.f32.bf16.bf16.f32 "
                 "{%0,%1,%2,%3}, {%4,%5,%6,%7}, {%8,%9}, {%0,%1,%2,%3};"
                 : "+f"(d[0]), "+f"(d[1]), "+f"(d[2]), "+f"(d[3])
                 : "r"(a[0]), "r"(a[1]), "r"(a[2]), "r"(a[3]), "r"(b[0]), "r"(b[1]));
}
__device__ __forceinline__ void cpa(u32 s, const void* g) {
    asm volatile("cp.async.cg.shared.global [%0], [%1], 16;" :: "r"(s), "l"(g));
}
#define CPC()  asm volatile("cp.async.commit_group;" ::: "memory")
#define CPW1() asm volatile("cp.async.wait_group 1;" ::: "memory")
#define CPW0() asm volatile("cp.async.wait_group 0;" ::: "memory")

__device__ __forceinline__ u32 pack_bf(bf16 a, bf16 b) {
    return (u32)__bfloat16_as_ushort(a) | ((u32)__bfloat16_as_ushort(b) << 16);
}
__device__ __forceinline__ void bsplit(float v, bf16& h, bf16& l) {
    h = __float2bfloat16(v);
    l = __float2bfloat16(v - __bfloat162float(h));
}
__device__ __forceinline__ u32 pack_h(float a, float b) {
    bf16 h0, l0, h1, l1; bsplit(a, h0, l0); bsplit(b, h1, l1); return pack_bf(h0, h1);
}
__device__ __forceinline__ u32 pack_l(float a, float b) {
    bf16 h0, l0, h1, l1; bsplit(a, h0, l0); bsplit(b, h1, l1); return pack_bf(l0, l1);
}

// swizzles (conflict-free for 8-row ldsm phases)
__device__ __forceinline__ u32 SWZ(int row, int c) {           // 64B rows
    return (u32)(row * 64 + ((c ^ ((row >> 1) & 3)) << 4));
}
__device__ __forceinline__ u32 swzU(int j, int c16) {          // 512B rows
    return (u32)(j * 512 + ((((c16 ^ j) & 7) | (c16 & 24)) << 4));
}
__device__ __forceinline__ u32 swzW(int m, int c16) {          // 256B rows
    return (u32)(m * 256 + ((((c16 ^ m) & 7) | (c16 & 8)) << 4));
}
__device__ __forceinline__ u32 swzT(int r, int c16) {          // 128B rows
    return (u32)(r * 128 + ((c16 ^ (r & 7)) << 4));
}

// ---------------- K0: split trig tables ----------------
__global__ void k_tables() {
    int a = blockIdx.x, b = threadIdx.x;
    int s = b & 63, k = s - 32;
    int q = ((k * a) % 256 + 256) % 256;
    float sv, cv;
    sincospif((float)q * (1.0f / 128.0f), &sv, &cv);
    float tc = (b < 64) ? cv : sv;
    bf16 h, l;
    bsplit(tc, h, l);
    g_Tch[b * 256 + a] = h; g_Tcl[b * 256 + a] = l;
    g_T5h[a * 128 + b] = h; g_T5l[a * 128 + b] = l;
    int c = b >> 6;
    float a5 = c ? (cv - sv) : (cv + sv);
    bsplit(a5, h, l);
    g_A5h[(c * 256 + a) * 64 + s] = h;
    g_A5l[(c * 256 + a) * 64 + s] = l;
}

// ---------------- Kw: weight transpose + split: w[i,o,xy] -> Wt[xy][o*64+i] ----------------
__global__ __launch_bounds__(256) void k_wt(const float* __restrict__ w) {
    __shared__ float tile[64][65];
    int bx = blockIdx.x;   // xy chunk (64 wide)
    int o = blockIdx.y;    // output channel
    int tid = threadIdx.x;
    int tx = tid & 63, tg = tid >> 6;
#pragma unroll
    for (int it = 0; it < 16; it++) {
        int i = tg + it * 4;
        tile[i][tx] = w[(size_t)(i * 64 + o) * 4096 + bx * 64 + tx];
    }
    __syncthreads();
#pragma unroll
    for (int it = 0; it < 16; it++) {
        int xy = tg + it * 4;
        float v = tile[tx][xy];
        bf16 h, l;
        bsplit(v, h, l);
        size_t dst = (size_t)(bx * 64 + xy) * 4096 + o * 64 + tx;
        g_Wth[dst] = h;
        g_Wtl[dst] = l;
    }
}

// ---------------- K12: fused forward (per image) ----------------
// smem: Ut_h @0 (64K), Ut_l @65536 (64K), pipeline @131072 (96K)
__global__ __launch_bounds__(512, 1) void k12(const float* __restrict__ x) {
    extern __shared__ char smem[];
    u32 sb = smem_u32(smem);
    const int PIPE = 131072;
    int tid = threadIdx.x, lane = tid & 31, w = tid >> 5;
    int wy = w >> 2, wx = w & 3;        // 4x4 warp grid
    int img = blockIdx.x;
    int g = lane >> 2, cp2 = (lane & 3) * 2;
    int rA = wy * 32 + (lane & 15), cA = lane >> 4;
    int rB = wx * 32 + (lane & 7) + ((lane >> 4) << 3), cB = (lane >> 3) & 1;

    // ======== K1: two passes over m-halves ========
    for (int mh = 0; mh < 2; mh++) {
        const float* xb = x + (size_t)img * 65536 + mh * 128 * 256;
        const int xrow = tid >> 2, xq = tid & 3;
        float c[2][4][4];
#pragma unroll
        for (int i = 0; i < 2; i++)
#pragma unroll
            for (int j = 0; j < 4; j++)
#pragma unroll
                for (int r = 0; r < 4; r++) c[i][j][r] = 0.f;
#pragma unroll
        for (int st = 0; st < 2; st++) {
            u32 b = sb + PIPE + st * 32768;
            cpa(b + SWZ(xrow, xq), &g_Tch[xrow * 256 + st * 32 + xq * 8]);
            cpa(b + 8192 + SWZ(xrow, xq), &g_Tcl[xrow * 256 + st * 32 + xq * 8]);
            CPC();
            const float* s = &xb[xrow * 256 + st * 32 + xq * 8];
            float4 v0 = *(const float4*)s, v1 = *(const float4*)(s + 4);
            u32 h4[4] = {pack_h(v0.x, v0.y), pack_h(v0.z, v0.w), pack_h(v1.x, v1.y), pack_h(v1.z, v1.w)};
            u32 l4[4] = {pack_l(v0.x, v0.y), pack_l(v0.z, v0.w), pack_l(v1.x, v1.y), pack_l(v1.z, v1.w)};
            *(uint4*)(smem + PIPE + st * 32768 + 16384 + SWZ(xrow, xq)) = *(uint4*)h4;
            *(uint4*)(smem + PIPE + st * 32768 + 24576 + SWZ(xrow, xq)) = *(uint4*)l4;
        }
        const int NCH = 8;
        for (int ch = 0; ch < NCH; ch++) {
            if (ch + 1 < NCH) { CPW1(); } else { CPW0(); }
            __syncthreads();
            bool pre = (ch + 2 < NCH);
            float4 v0, v1;
            if (pre) {
                const float* s = &xb[xrow * 256 + (ch + 2) * 32 + xq * 8];
                v0 = *(const float4*)s; v1 = *(const float4*)(s + 4);
                u32 b = sb + PIPE + ((ch + 2) % 3) * 32768;
                cpa(b + SWZ(xrow, xq), &g_Tch[xrow * 256 + (ch + 2) * 32 + xq * 8]);
                cpa(b + 8192 + SWZ(xrow, xq), &g_Tcl[xrow * 256 + (ch + 2) * 32 + xq * 8]);
                CPC();
            }
            u32 base = sb + PIPE + (ch % 3) * 32768;
#pragma unroll
            for (int kk = 0; kk < 2; kk++) {
                int kc = kk * 2;
                u32 ah[2][4], al[2][4], bh[2][4], bl[2][4];
#pragma unroll
                for (int mi = 0; mi < 2; mi++) {
                    u32 ao = SWZ(rA + mi * 16, kc + cA);
                    ldsm4(ah[mi], base + ao);
                    ldsm4(al[mi], base + 8192 + ao);
                }
#pragma unroll
                for (int np = 0; np < 2; np++) {
                    u32 bo = SWZ(rB + np * 16, kc + cB);
                    ldsm4(bh[np], base + 16384 + bo);
                    ldsm4(bl[np], base + 24576 + bo);
                }
#pragma unroll
                for (int mi = 0; mi < 2; mi++)
#pragma unroll
                    for (int ni = 0; ni < 4; ni++)
                        mmabf(c[mi][ni], ah[mi], &bh[ni >> 1][(ni & 1) * 2]);
#pragma unroll
                for (int mi = 0; mi < 2; mi++)
#pragma unroll
                    for (int ni = 0; ni < 4; ni++)
                        mmabf(c[mi][ni], ah[mi], &bl[ni >> 1][(ni & 1) * 2]);
#pragma unroll
                for (int mi = 0; mi < 2; mi++)
#pragma unroll
                    for (int ni = 0; ni < 4; ni++)
                        mmabf(c[mi][ni], al[mi], &bh[ni >> 1][(ni & 1) * 2]);
            }
            if (pre) {
                u32 h4[4] = {pack_h(v0.x, v0.y), pack_h(v0.z, v0.w), pack_h(v1.x, v1.y), pack_h(v1.z, v1.w)};
                u32 l4[4] = {pack_l(v0.x, v0.y), pack_l(v0.z, v0.w), pack_l(v1.x, v1.y), pack_l(v1.z, v1.w)};
                u32 o = PIPE + ((ch + 2) % 3) * 32768;
                *(uint4*)(smem + o + 16384 + SWZ(xrow, xq)) = *(uint4*)h4;
                *(uint4*)(smem + o + 24576 + SWZ(xrow, xq)) = *(uint4*)l4;
            }
        }
#pragma unroll
        for (int mi = 0; mi < 2; mi++)
#pragma unroll
            for (int ni = 0; ni < 4; ni++) {
                int m = mh * 128 + wx * 32 + ni * 8 + cp2;
                int j0 = wy * 32 + mi * 16 + g;
                float* d = c[mi][ni];
                u32 a0 = swzU(j0, m >> 3) + (m & 7) * 2;
                u32 a1 = swzU(j0 + 8, m >> 3) + (m & 7) * 2;
                *(u32*)(smem + a0) = pack_h(d[0], d[1]);
                *(u32*)(smem + 65536 + a0) = pack_l(d[0], d[1]);
                *(u32*)(smem + a1) = pack_h(d[2], d[3]);
                *(u32*)(smem + 65536 + a1) = pack_l(d[2], d[3]);
            }
        __syncthreads();
    }

    // ======== K2: B from smem Ut ========
    {
        const int xrow = tid >> 2, xq = tid & 3;
        float c[2][4][4];
#pragma unroll
        for (int i = 0; i < 2; i++)
#pragma unroll
            for (int j = 0; j < 4; j++)
#pragma unroll
                for (int r = 0; r < 4; r++) c[i][j][r] = 0.f;
#pragma unroll
        for (int st = 0; st < 2; st++) {
            u32 b = sb + PIPE + st * 16384;
            cpa(b + SWZ(xrow, xq), &g_Tch[xrow * 256 + st * 32 + xq * 8]);
            cpa(b + 8192 + SWZ(xrow, xq), &g_Tcl[xrow * 256 + st * 32 + xq * 8]);
            CPC();
        }
        const int NCH = 8;
        for (int ch = 0; ch < NCH; ch++) {
            if (ch + 1 < NCH) { CPW1(); } else { CPW0(); }
            __syncthreads();
            if (ch + 2 < NCH) {
                u32 b = sb + PIPE + ((ch + 2) % 3) * 16384;
                cpa(b + SWZ(xrow, xq), &g_Tch[xrow * 256 + (ch + 2) * 32 + xq * 8]);
                cpa(b + 8192 + SWZ(xrow, xq), &g_Tcl[xrow * 256 + (ch + 2) * 32 + xq * 8]);
                CPC();
            }
            u32 base = sb + PIPE + (ch % 3) * 16384;
#pragma unroll
            for (int kk = 0; kk < 2; kk++) {
                u32 ah[2][4], al[2][4], bh[2][4], bl[2][4];
#pragma unroll
                for (int mi = 0; mi < 2; mi++) {
                    u32 ao = SWZ(rA + mi * 16, kk * 2 + cA);
                    ldsm4(ah[mi], base + ao);
                    ldsm4(al[mi], base + 8192 + ao);
                }
#pragma unroll
                for (int np = 0; np < 2; np++) {
                    int c16 = ch * 4 + kk * 2 + cB;
                    u32 bo = swzU(rB + np * 16, c16);
                    ldsm4(bh[np], sb + bo);
                    ldsm4(bl[np], sb + 65536 + bo);
                }
#pragma unroll
                for (int mi = 0; mi < 2; mi++)
#pragma unroll
                    for (int ni = 0; ni < 4; ni++)
                        mmabf(c[mi][ni], ah[mi], &bh[ni >> 1][(ni & 1) * 2]);
#pragma unroll
                for (int mi = 0; mi < 2; mi++)
#pragma unroll
                    for (int ni = 0; ni < 4; ni++)
                        mmabf(c[mi][ni], ah[mi], &bl[ni >> 1][(ni & 1) * 2]);
#pragma unroll
                for (int mi = 0; mi < 2; mi++)
#pragma unroll
                    for (int ni = 0; ni < 4; ni++)
                        mmabf(c[mi][ni], al[mi], &bh[ni >> 1][(ni & 1) * 2]);
            }
        }
        __syncthreads();
        float* F = (float*)(smem + PIPE);
#pragma unroll
        for (int mi = 0; mi < 2; mi++)
#pragma unroll
            for (int ni = 0; ni < 4; ni++) {
                int col = wx * 32 + ni * 8 + cp2;
                int r0 = wy * 32 + mi * 16 + g;
                float* d = c[mi][ni];
                F[r0 * 132 + col] = d[0];
                F[r0 * 132 + col + 1] = d[1];
                F[(r0 + 8) * 132 + col] = d[2];
                F[(r0 + 8) * 132 + col + 1] = d[3];
            }
        __syncthreads();
        const int b = img >> 6, ic = img & 63;
#pragma unroll
        for (int t = 0; t < 8; t++) {
            int p = tid + t * 512;
            int s1 = p >> 6, s2 = p & 63;
            float r00 = F[s1 * 132 + s2];
            float r01 = F[s1 * 132 + 64 + s2];
            float r10 = F[(64 + s1) * 132 + s2];
            float r11 = F[(64 + s1) * 132 + 64 + s2];
            int a = p * 1024 + ic * 16 + b;
            g_CS[a] = r00 - r11;
            g_CS[4194304 + a] = r10 + r01;
        }
    }
}

// ---------------- K3: paired channel mixing (split-bf16 HMMA) ----------------
// Processes mode m0 AND its flip f0 in one block (halves weight traffic).
// smem: A tiles 8x2KB @0 (Ch0,Cl0,Sh0,Sl0,Ch1,Cl1,Sh1,Sl1), W 4x8KB @16384
__global__ __launch_bounds__(256) void k_mix() {
    __shared__ __align__(16) char sm[49152];
    u32 sb = smem_u32(sm);
    const int m0 = blockIdx.x;
    const int s1 = m0 >> 6, s2 = m0 & 63;
    const int f1 = (64 - s1) & 63, f2 = (64 - s2) & 63;
    const int f0 = f1 * 64 + f2;
    if (m0 > f0) return;
    const bool dual = (f0 != m0);
    const int tid = threadIdx.x, lane = tid & 31, w = tid >> 5;

    // W tiles: W(m0) @16384/24576, W(f0) @32768/40960
#pragma unroll
    for (int t = 0; t < 2; t++) {
        int f = tid + t * 256;
        int o = f >> 3, c16 = f & 7;
        size_t src = (size_t)m0 * 4096 + o * 64 + c16 * 8;
        size_t srcf = (size_t)f0 * 4096 + o * 64 + c16 * 8;
        cpa(sb + 16384 + swzT(o, c16), &g_Wth[src]);
        cpa(sb + 24576 + swzT(o, c16), &g_Wtl[src]);
        cpa(sb + 32768 + swzT(o, c16), &g_Wth[srcf]);
        cpa(sb + 40960 + swzT(o, c16), &g_Wtl[srcf]);
    }
    CPC();
    // CS fp32 -> split bf16 A tiles for both modes
    {
        float4 cv = *(const float4*)&g_CS[m0 * 1024 + tid * 4];
        float4 sv = *(const float4*)&g_CS[4194304 + m0 * 1024 + tid * 4];
        float cva[4] = {cv.x, cv.y, cv.z, cv.w}, sva[4] = {sv.x, sv.y, sv.z, sv.w};
#pragma unroll
        for (int q = 0; q < 4; q++) {
            int j = tid * 4 + q;
            int b = j & 15, ci = j >> 4;
            u32 a = swzT(b, ci >> 3) + (ci & 7) * 2;
            bf16 h, l;
            bsplit(cva[q], h, l);
            *(unsigned short*)(sm + a) = __bfloat16_as_ushort(h);
            *(unsigned short*)(sm + 2048 + a) = __bfloat16_as_ushort(l);
            bsplit(sva[q], h, l);
            *(unsigned short*)(sm + 4096 + a) = __bfloat16_as_ushort(h);
            *(unsigned short*)(sm + 6144 + a) = __bfloat16_as_ushort(l);
        }
        if (dual) {
            float4 cvf = *(const float4*)&g_CS[f0 * 1024 + tid * 4];
            float4 svf = *(const float4*)&g_CS[4194304 + f0 * 1024 + tid * 4];
            float cvb[4] = {cvf.x, cvf.y, cvf.z, cvf.w}, svb[4] = {svf.x, svf.y, svf.z, svf.w};
#pragma unroll
            for (int q = 0; q < 4; q++) {
                int j = tid * 4 + q;
                int b = j & 15, ci = j >> 4;
                u32 a = swzT(b, ci >> 3) + (ci & 7) * 2;
                bf16 h, l;
                bsplit(cvb[q], h, l);
                *(unsigned short*)(sm + 8192 + a) = __bfloat16_as_ushort(h);
                *(unsigned short*)(sm + 10240 + a) = __bfloat16_as_ushort(l);
                bsplit(svb[q], h, l);
                *(unsigned short*)(sm + 12288 + a) = __bfloat16_as_ushort(h);
                *(unsigned short*)(sm + 14336 + a) = __bfloat16_as_ushort(l);
            }
        }
    }
    CPW0();
    __syncthreads();
    // warp w -> n8 slice of o
    float acc0[4] = {0.f, 0.f, 0.f, 0.f};
    float acc1[4] = {0.f, 0.f, 0.f, 0.f};
    const int o0 = w * 8;
    const int arow = lane & 15, ac = lane >> 4;
    const int brow = o0 + (lane & 7), bc = (lane >> 3) & 1;
#pragma unroll
    for (int kc = 0; kc < 4; kc++) {
        u32 ao = swzT(arow, kc * 2 + ac);
        u32 bo = swzT(brow, kc * 2 + bc);
        u32 bh[2], bl[2], brh[2], brl[2];
        ldsm2(bh, sb + 16384 + bo);
        ldsm2(bl, sb + 24576 + bo);
        ldsm2(brh, sb + 32768 + bo);
        ldsm2(brl, sb + 40960 + bo);
        {   // mode m0: C0*W + S0*Wr
            u32 ach[4], acl[4], ash[4], asl[4];
            ldsm4(ach, sb + ao);
            ldsm4(acl, sb + 2048 + ao);
            ldsm4(ash, sb + 4096 + ao);
            ldsm4(asl, sb + 6144 + ao);
            mmabf(acc0, ach, bh);
            mmabf(acc0, ach, bl);
            mmabf(acc0, acl, bh);
            mmabf(acc0, ash, brh);
            mmabf(acc0, ash, brl);
            mmabf(acc0, asl, brh);
        }
        if (dual) {  // mode f0: C1*Wr + S1*W
            u32 ach[4], acl[4], ash[4], asl[4];
            ldsm4(ach, sb + 8192 + ao);
            ldsm4(acl, sb + 10240 + ao);
            ldsm4(ash, sb + 12288 + ao);
            ldsm4(asl, sb + 14336 + ao);
            mmabf(acc1, ach, brh);
            mmabf(acc1, ach, brl);
            mmabf(acc1, acl, brh);
            mmabf(acc1, ash, bh);
            mmabf(acc1, ash, bl);
            mmabf(acc1, asl, bh);
        }
    }
    // epilogue
    const int g = lane >> 2, cp2 = (lane & 3) * 2;
    const int tpos0 = s2 * 64 + s1;
    const int tpos1 = f2 * 64 + f1;
#pragma unroll
    for (int half = 0; half < 2; half++) {
        int b = g + half * 8;
        bf16 h, l;
        bsplit(acc0[half * 2], h, l);
        g_Ttp[(size_t)(b * 64 + o0 + cp2) * 4096 + tpos0] = pack_bf(h, l);
        bsplit(acc0[half * 2 + 1], h, l);
        g_Ttp[(size_t)(b * 64 + o0 + cp2 + 1) * 4096 + tpos0] = pack_bf(h, l);
        if (dual) {
            bsplit(acc1[half * 2], h, l);
            g_Ttp[(size_t)(b * 64 + o0 + cp2) * 4096 + tpos1] = pack_bf(h, l);
            bsplit(acc1[half * 2 + 1], h, l);
            g_Ttp[(size_t)(b * 64 + o0 + cp2 + 1) * 4096 + tpos1] = pack_bf(h, l);
        }
    }
}

// ---------------- K45: fused inverse (per image) ----------------
// smem: Wm_h @0 (64K), Wm_l @65536 (64K), pipeline @131072 (64K), Tt @196608 (16K)
__global__ __launch_bounds__(512, 1) void k45(const float* __restrict__ bias,
                                              float* __restrict__ out) {
    extern __shared__ char smem[];
    u32 sb = smem_u32(smem);
    const int PIPE = 131072, TT = 196608;
    int tid = threadIdx.x, lane = tid & 31, w = tid >> 5;
    int wy = w >> 1, wx = w & 1;        // 8x2 warp grid
    int img = blockIdx.x;
    int g = lane >> 2, cp2 = (lane & 3) * 2;

    auto issueA = [&](int slot) {
        int cc = slot >> 1, k0 = (slot & 1) * 32;
        const bf16* Ah = g_A5h + cc * 16384;
        const bf16* Al = g_A5l + cc * 16384;
        u32 b = sb + PIPE + (slot & 1) * 32768;
#pragma unroll
        for (int t = 0; t < 2; t++) {
            int f = tid + t * 512, row = f >> 2, q = f & 3;
            cpa(b + SWZ(row, q), &Ah[row * 64 + k0 + q * 8]);
            cpa(b + 16384 + SWZ(row, q), &Al[row * 64 + k0 + q * 8]);
        }
        CPC();
    };
    issueA(0); issueA(1);

    // unpack packed Tot into h/l swizzled tiles
#pragma unroll
    for (int t = 0; t < 8; t++) {
        int p = tid + t * 512;
        u32 v = g_Ttp[(size_t)img * 4096 + p];
        int r = p >> 6, cc = p & 63;
        u32 a = swzT(r, cc >> 3) + (cc & 7) * 2;
        *(unsigned short*)(smem + TT + a) = (unsigned short)(v & 0xFFFF);
        *(unsigned short*)(smem + TT + 8192 + a) = (unsigned short)(v >> 16);
    }

    // ======== K4: two c-passes ========
    int rA = wy * 32 + (lane & 15), cA = lane >> 4;
    int rB = wx * 32 + (lane & 7) + ((lane >> 4) << 3), cB = (lane >> 3) & 1;
    for (int cpass = 0; cpass < 2; cpass++) {
        float acc[2][4][4];
#pragma unroll
        for (int i = 0; i < 2; i++)
#pragma unroll
            for (int j = 0; j < 4; j++)
#pragma unroll
                for (int r = 0; r < 4; r++) acc[i][j][r] = 0.f;
        for (int k = 0; k < 2; k++) {
            int slot = cpass * 2 + k;
            if (slot < 3) { CPW1(); } else { CPW0(); }
            __syncthreads();
            u32 stg = sb + PIPE + (slot & 1) * 32768;
#pragma unroll
            for (int kk = 0; kk < 2; kk++) {
                u32 ah[2][4], al[2][4], bh[2][4], bl[2][4];
#pragma unroll
                for (int mi = 0; mi < 2; mi++) {
                    u32 ao = SWZ(rA + mi * 16, kk * 2 + cA);
                    ldsm4(ah[mi], stg + ao);
                    ldsm4(al[mi], stg + 16384 + ao);
                }
#pragma unroll
                for (int np = 0; np < 2; np++) {
                    int c16 = k * 4 + kk * 2 + cB;
                    u32 bo = swzT(rB + np * 16, c16);
                    ldsm4(bh[np], sb + TT + bo);
                    ldsm4(bl[np], sb + TT + 8192 + bo);
                }
#pragma unroll
                for (int mi = 0; mi < 2; mi++)
#pragma unroll
                    for (int ni = 0; ni < 4; ni++)
                        mmabf(acc[mi][ni], ah[mi], &bh[ni >> 1][(ni & 1) * 2]);
#pragma unroll
                for (int mi = 0; mi < 2; mi++)
#pragma unroll
                    for (int ni = 0; ni < 4; ni++)
                        mmabf(acc[mi][ni], ah[mi], &bl[ni >> 1][(ni & 1) * 2]);
#pragma unroll
                for (int mi = 0; mi < 2; mi++)
#pragma unroll
                    for (int ni = 0; ni < 4; ni++)
                        mmabf(acc[mi][ni], al[mi], &bh[ni >> 1][(ni & 1) * 2]);
            }
            __syncthreads();
            if (slot + 2 < 4) issueA(slot + 2);
        }
#pragma unroll
        for (int mi = 0; mi < 2; mi++)
#pragma unroll
            for (int ni = 0; ni < 4; ni++) {
                int col = cpass * 64 + wx * 32 + ni * 8 + cp2;
                int m0 = wy * 32 + mi * 16 + g;
                float* d = acc[mi][ni];
                u32 a0 = swzW(m0, col >> 3) + (col & 7) * 2;
                u32 a1 = swzW(m0 + 8, col >> 3) + (col & 7) * 2;
                *(u32*)(smem + a0) = pack_h(d[0], d[1]);
                *(u32*)(smem + 65536 + a0) = pack_l(d[0], d[1]);
                *(u32*)(smem + a1) = pack_h(d[2], d[3]);
                *(u32*)(smem + 65536 + a1) = pack_l(d[2], d[3]);
            }
    }
    __syncthreads();

    // ======== K5: A from smem Wmat, B = T5 ring ========
    const float bv = bias[img & 63];
    const float sc = 1.0f / 65536.0f;
    int rB5 = wx * 64 + (lane & 7) + ((lane >> 4) << 3);
    for (int nh = 0; nh < 2; nh++) {
        float c5[2][8][4];
#pragma unroll
        for (int i = 0; i < 2; i++)
#pragma unroll
            for (int j = 0; j < 8; j++)
#pragma unroll
                for (int r = 0; r < 4; r++) c5[i][j][r] = 0.f;
        int xrow = tid >> 2, xq = tid & 3;
#pragma unroll
        for (int st = 0; st < 2; st++) {
            u32 b = sb + PIPE + st * 16384;
            cpa(b + SWZ(xrow, xq), &g_T5h[(nh * 128 + xrow) * 128 + st * 32 + xq * 8]);
            cpa(b + 8192 + SWZ(xrow, xq), &g_T5l[(nh * 128 + xrow) * 128 + st * 32 + xq * 8]);
            CPC();
        }
        for (int ch = 0; ch < 4; ch++) {
            if (ch < 3) { CPW1(); } else { CPW0(); }
            __syncthreads();
            if (ch + 2 < 4) {
                u32 b = sb + PIPE + ((ch + 2) % 3) * 16384;
                cpa(b + SWZ(xrow, xq), &g_T5h[(nh * 128 + xrow) * 128 + (ch + 2) * 32 + xq * 8]);
                cpa(b + 8192 + SWZ(xrow, xq), &g_T5l[(nh * 128 + xrow) * 128 + (ch + 2) * 32 + xq * 8]);
                CPC();
            }
            u32 stg = sb + PIPE + (ch % 3) * 16384;
#pragma unroll
            for (int kk = 0; kk < 2; kk++) {
                u32 ah[2][4], al[2][4], bh[4][4], bl[4][4];
#pragma unroll
                for (int mi = 0; mi < 2; mi++) {
                    int c16 = ch * 4 + kk * 2 + cA;
                    u32 ao = swzW(rA + mi * 16, c16);
                    ldsm4(ah[mi], sb + ao);
                    ldsm4(al[mi], sb + 65536 + ao);
                }
#pragma unroll
                for (int np = 0; np < 4; np++) {
                    u32 bo = SWZ(rB5 + np * 16, kk * 2 + cB);
                    ldsm4(bh[np], stg + bo);
                    ldsm4(bl[np], stg + 8192 + bo);
                }
#pragma unroll
                for (int mi = 0; mi < 2; mi++)
#pragma unroll
                    for (int ni = 0; ni < 8; ni++)
                        mmabf(c5[mi][ni], ah[mi], &bh[ni >> 1][(ni & 1) * 2]);
#pragma unroll
                for (int mi = 0; mi < 2; mi++)
#pragma unroll
                    for (int ni = 0; ni < 8; ni++)
                        mmabf(c5[mi][ni], ah[mi], &bl[ni >> 1][(ni & 1) * 2]);
#pragma unroll
                for (int mi = 0; mi < 2; mi++)
#pragma unroll
                    for (int ni = 0; ni < 8; ni++)
                        mmabf(c5[mi][ni], al[mi], &bh[ni >> 1][(ni & 1) * 2]);
            }
        }
#pragma unroll
        for (int mi = 0; mi < 2; mi++)
#pragma unroll
            for (int ni = 0; ni < 8; ni++) {
                int col = nh * 128 + wx * 64 + ni * 8 + cp2;
                float* d = c5[mi][ni];
#pragma unroll
                for (int half = 0; half < 2; half++) {
                    int m = wy * 32 + mi * 16 + g + half * 8;
                    float2 v;
                    v.x = fmaxf(fmaf(d[half * 2], sc, bv), 0.f);
                    v.y = fmaxf(fmaf(d[half * 2 + 1], sc, bv), 0.f);
                    *(float2*)&out[(size_t)img * 65536 + m * 256 + col] = v;
                }
            }
        __syncthreads();
    }
}

extern "C" void kernel_launch(void* const* d_in, const int* in_sizes, int n_in,
                              void* d_out, int out_size) {
    const float* x = (const float*)d_in[0];
    const float* wgt = (const float*)d_in[1];
    const float* bias = (const float*)d_in[2];
    float* out = (float*)d_out;

    static cudaStream_t side = nullptr;
    static cudaEvent_t evFork = nullptr, evJoin = nullptr;
    if (!side) {
        cudaStreamCreateWithFlags(&side, cudaStreamNonBlocking);
        cudaEventCreateWithFlags(&evFork, cudaEventDisableTiming);
        cudaEventCreateWithFlags(&evJoin, cudaEventDisableTiming);
    }
    cudaFuncSetAttribute(k12, cudaFuncAttributeMaxDynamicSharedMemorySize, 229376);
    cudaFuncSetAttribute(k45, cudaFuncAttributeMaxDynamicSharedMemorySize, 212992);

    // fork: k_wt runs on side stream, overlapping k12
    cudaEventRecord(evFork, 0);
    cudaStreamWaitEvent(side, evFork, 0);
    k_wt<<<dim3(64, 64), 256, 0, side>>>(wgt);
    cudaEventRecord(evJoin, side);

    k_tables<<<256, 128>>>();
    k12<<<1024, 512, 229376>>>(x);

    cudaStreamWaitEvent(0, evJoin, 0);   // join before k_mix (needs weights)
    k_mix<<<4096, 256>>>();
    k45<<<1024, 512, 212992>>>(bias, out);
}